// round 1
// baseline (speedup 1.0000x reference)
#include <cuda_runtime.h>
#include <cuda_bf16.h>

// Problem constants
#define BATCH   4
#define DIM     384
#define HEADS   8
#define DHEAD   64
#define INNER   512          // HEADS*DHEAD
#define QKV_CH  1536         // 3*INNER
#define IMG_H   56
#define IMG_W   56
#define HW      3136         // 56*56
#define SCALE   0.125f       // 64^-0.5

// Scratch (device globals: no allocation allowed)
__device__ float g_qkv[(long)BATCH * QKV_CH * HW];   // q:[0,512) k:[512,1024) v:[1024,1536) channels
__device__ float g_ao [(long)BATCH * INNER * HW];    // attention output, channel-major

// ---------------------------------------------------------------------------
// SIMT fp32 GEMM: C[b] (MxN) = A (MxK, row-major) @ B[b] (KxN, row-major)
// A rows >= `split` come from A1 (row - split); below from A0. Optional bias.
// BM=128, BN=64, BK=8, 256 threads, 8x4 per-thread tile.
// Requires: M%128==0, N%64==0 (N%4==0 for float4), K%8==0.
// ---------------------------------------------------------------------------
#define BM 128
#define BN 64
#define BK 8
#define TM 8
#define TN 4

__global__ __launch_bounds__(256) void gemm_kernel(
    const float* __restrict__ A0,
    const float* __restrict__ A1, int split,
    const float* __restrict__ Bm,
    const float* __restrict__ bias,
    float* __restrict__ C,
    int M, int N, int K,
    long strideB, long strideC)
{
    __shared__ float As[BK][BM];
    __shared__ float Bs[BK][BN];

    const int tid = threadIdx.x;
    const int bx = blockIdx.x;   // N tile
    const int by = blockIdx.y;   // M tile
    const int bz = blockIdx.z;   // batch

    const float* Bbase = Bm + (long)bz * strideB;
    float*       Cbase = C  + (long)bz * strideC;

    const int row0 = by * BM;
    const int col0 = bx * BN;

    const float* Abase = (row0 >= split) ? (A1 + (long)(row0 - split) * K)
                                         : (A0 + (long)row0 * K);

    // A-tile load mapping: 1024 floats, 256 threads * 1 float4
    const int a_row = tid >> 1;          // 0..127
    const int a_k4  = (tid & 1) * 4;     // 0 or 4
    // B-tile load mapping: 512 floats, first 128 threads * 1 float4
    const int b_k  = tid >> 4;           // 0..15 (use only <8, i.e. tid<128)
    const int b_c4 = (tid & 15) * 4;

    const int ty = tid >> 4;             // 0..15 -> rows ty*8..ty*8+7
    const int tx = tid & 15;             // 0..15 -> cols tx*4..tx*4+3

    float acc[TM][TN];
    #pragma unroll
    for (int i = 0; i < TM; i++)
        #pragma unroll
        for (int j = 0; j < TN; j++)
            acc[i][j] = 0.f;

    for (int kt = 0; kt < K; kt += BK) {
        // Stage A (transposed) and B
        float4 av = *(const float4*)(Abase + (long)a_row * K + kt + a_k4);
        As[a_k4 + 0][a_row] = av.x;
        As[a_k4 + 1][a_row] = av.y;
        As[a_k4 + 2][a_row] = av.z;
        As[a_k4 + 3][a_row] = av.w;
        if (tid < 128) {
            float4 bv = *(const float4*)(Bbase + (long)(kt + b_k) * N + col0 + b_c4);
            *(float4*)&Bs[b_k][b_c4] = bv;
        }
        __syncthreads();

        #pragma unroll
        for (int kk = 0; kk < BK; kk++) {
            float af[TM], bf[TN];
            float4 a0 = *(const float4*)&As[kk][ty * TM + 0];
            float4 a1 = *(const float4*)&As[kk][ty * TM + 4];
            af[0]=a0.x; af[1]=a0.y; af[2]=a0.z; af[3]=a0.w;
            af[4]=a1.x; af[5]=a1.y; af[6]=a1.z; af[7]=a1.w;
            float4 b0 = *(const float4*)&Bs[kk][tx * TN];
            bf[0]=b0.x; bf[1]=b0.y; bf[2]=b0.z; bf[3]=b0.w;
            #pragma unroll
            for (int i = 0; i < TM; i++)
                #pragma unroll
                for (int j = 0; j < TN; j++)
                    acc[i][j] = fmaf(af[i], bf[j], acc[i][j]);
        }
        __syncthreads();
    }

    // Write back (+bias)
    #pragma unroll
    for (int i = 0; i < TM; i++) {
        const int row = row0 + ty * TM + i;
        const float bv = bias ? bias[row] : 0.f;
        float4 o;
        o.x = acc[i][0] + bv;
        o.y = acc[i][1] + bv;
        o.z = acc[i][2] + bv;
        o.w = acc[i][3] + bv;
        *(float4*)(Cbase + (long)row * N + col0 + tx * TN) = o;
    }
}

// ---------------------------------------------------------------------------
// Neighborhood attention: 3x3 window, softmax over 9 taps, zero-padded taps
// participate with logit 0 and v=0 (matches F.unfold zero padding).
// One thread per (b, head, y, x). qkv channel-major: (b, ch, y, x).
// ---------------------------------------------------------------------------
__global__ __launch_bounds__(64) void attn_kernel(
    const float* __restrict__ qkv, float* __restrict__ ao)
{
    const int x = threadIdx.x;
    if (x >= IMG_W) return;
    const int y = blockIdx.x;
    const int bh = blockIdx.y;
    const int head = bh & (HEADS - 1);
    const int b = bh >> 3;

    const float* q = qkv + ((long)b * QKV_CH + head * DHEAD) * HW;
    const float* k = q + (long)INNER * HW;
    const float* v = q + 2L * INNER * HW;
    const int p = y * IMG_W + x;

    // Tap offsets + validity (row-major over (dy,dx), matching unfold order)
    bool valid[9];
    int off[9];
    #pragma unroll
    for (int t = 0; t < 9; t++) {
        const int dy = t / 3 - 1;
        const int dx = t % 3 - 1;
        const int yy = y + dy;
        const int xx = x + dx;
        valid[t] = (yy >= 0) && (yy < IMG_H) && (xx >= 0) && (xx < IMG_W);
        off[t] = valid[t] ? (yy * IMG_W + xx) : 0;
    }

    float dots[9];
    #pragma unroll
    for (int t = 0; t < 9; t++) dots[t] = 0.f;

    #pragma unroll 4
    for (int d = 0; d < DHEAD; d++) {
        const long dp = (long)d * HW;
        const float qv = q[dp + p];
        #pragma unroll
        for (int t = 0; t < 9; t++) {
            const float kv = valid[t] ? k[dp + off[t]] : 0.f;
            dots[t] = fmaf(qv, kv, dots[t]);
        }
    }

    float m = -1e30f;
    #pragma unroll
    for (int t = 0; t < 9; t++) {
        dots[t] *= SCALE;          // invalid taps: 0*SCALE = 0 (padded-logit semantics)
        m = fmaxf(m, dots[t]);
    }
    float w[9];
    float s = 0.f;
    #pragma unroll
    for (int t = 0; t < 9; t++) {
        w[t] = __expf(dots[t] - m);
        s += w[t];
    }
    const float inv = 1.f / s;
    #pragma unroll
    for (int t = 0; t < 9; t++) w[t] *= inv;

    float* o = ao + ((long)b * INNER + head * DHEAD) * HW;
    #pragma unroll 4
    for (int d = 0; d < DHEAD; d++) {
        const long dp = (long)d * HW;
        float a = 0.f;
        #pragma unroll
        for (int t = 0; t < 9; t++) {
            const float vv = valid[t] ? v[dp + off[t]] : 0.f;
            a = fmaf(w[t], vv, a);
        }
        o[dp + p] = a;
    }
}

// ---------------------------------------------------------------------------
extern "C" void kernel_launch(void* const* d_in, const int* in_sizes, int n_in,
                              void* d_out, int out_size)
{
    const float* x   = (const float*)d_in[0];   // (4,384,56,56)
    const float* Wq  = (const float*)d_in[1];   // (512,384)
    const float* Wkv = (const float*)d_in[2];   // (1024,384)
    const float* Wo  = (const float*)d_in[3];   // (384,512)
    const float* bo  = (const float*)d_in[4];   // (384,)
    float* out = (float*)d_out;                 // (4,384,56,56)

    float* qkv; cudaGetSymbolAddress((void**)&qkv, g_qkv);
    float* ao;  cudaGetSymbolAddress((void**)&ao,  g_ao);

    // 1) fused q+kv projection: [1536x384] @ [384x3136] per batch
    {
        dim3 grid(HW / BN, QKV_CH / BM, BATCH);
        gemm_kernel<<<grid, 256>>>(Wq, Wkv, INNER, x, nullptr, qkv,
                                   QKV_CH, HW, DIM,
                                   (long)DIM * HW, (long)QKV_CH * HW);
    }

    // 2) neighborhood attention
    {
        dim3 grid(IMG_H, BATCH * HEADS);
        attn_kernel<<<grid, 64>>>(qkv, ao);
    }

    // 3) output projection + bias: [384x512] @ [512x3136] per batch
    {
        dim3 grid(HW / BN, DIM / BM, BATCH);
        gemm_kernel<<<grid, 256>>>(Wo, Wo, 1 << 30, ao, bo, out,
                                   DIM, HW, INNER,
                                   (long)INNER * HW, (long)DIM * HW);
    }
}

// round 2
// speedup vs baseline: 1.0011x; 1.0011x over previous
#include <cuda_runtime.h>
#include <cuda_bf16.h>

// Problem constants
#define BATCH   4
#define DIM     384
#define HEADS   8
#define DHEAD   64
#define INNER   512          // HEADS*DHEAD
#define QKV_CH  1536         // 3*INNER
#define IMG_H   56
#define IMG_W   56
#define HW      3136         // 56*56
#define SCALE   0.125f       // 64^-0.5

// Scratch (device globals: no allocation allowed)
__device__ float g_qkv[(long)BATCH * QKV_CH * HW];   // q:[0,512) k:[512,1024) v:[1024,1536) channels
__device__ float g_ao [(long)BATCH * INNER * HW];    // attention output, channel-major

// ---------------------------------------------------------------------------
// SIMT fp32 GEMM: C[b] (MxN) = A (MxK, row-major) @ B[b] (KxN, row-major)
// A rows >= `split` come from A1 (row - split); below from A0. Optional bias.
// BM=128, BN=64, BK=8, 256 threads, 8x4 per-thread tile.
// Requires: M%128==0, N%64==0 (N%4==0 for float4), K%8==0.
// ---------------------------------------------------------------------------
#define BM 128
#define BN 64
#define BK 8
#define TM 8
#define TN 4

__global__ __launch_bounds__(256) void gemm_kernel(
    const float* __restrict__ A0,
    const float* __restrict__ A1, int split,
    const float* __restrict__ Bm,
    const float* __restrict__ bias,
    float* __restrict__ C,
    int M, int N, int K,
    long strideB, long strideC)
{
    __shared__ float As[BK][BM];
    __shared__ float Bs[BK][BN];

    const int tid = threadIdx.x;
    const int bx = blockIdx.x;   // N tile
    const int by = blockIdx.y;   // M tile
    const int bz = blockIdx.z;   // batch

    const float* Bbase = Bm + (long)bz * strideB;
    float*       Cbase = C  + (long)bz * strideC;

    const int row0 = by * BM;
    const int col0 = bx * BN;

    const float* Abase = (row0 >= split) ? (A1 + (long)(row0 - split) * K)
                                         : (A0 + (long)row0 * K);

    // A-tile load mapping: 1024 floats, 256 threads * 1 float4
    const int a_row = tid >> 1;          // 0..127
    const int a_k4  = (tid & 1) * 4;     // 0 or 4
    // B-tile load mapping: 512 floats, first 128 threads * 1 float4
    const int b_k  = tid >> 4;           // 0..15 (use only <8, i.e. tid<128)
    const int b_c4 = (tid & 15) * 4;

    const int ty = tid >> 4;             // 0..15 -> rows ty*8..ty*8+7
    const int tx = tid & 15;             // 0..15 -> cols tx*4..tx*4+3

    float acc[TM][TN];
    #pragma unroll
    for (int i = 0; i < TM; i++)
        #pragma unroll
        for (int j = 0; j < TN; j++)
            acc[i][j] = 0.f;

    for (int kt = 0; kt < K; kt += BK) {
        // Stage A (transposed) and B
        float4 av = *(const float4*)(Abase + (long)a_row * K + kt + a_k4);
        As[a_k4 + 0][a_row] = av.x;
        As[a_k4 + 1][a_row] = av.y;
        As[a_k4 + 2][a_row] = av.z;
        As[a_k4 + 3][a_row] = av.w;
        if (tid < 128) {
            float4 bv = *(const float4*)(Bbase + (long)(kt + b_k) * N + col0 + b_c4);
            *(float4*)&Bs[b_k][b_c4] = bv;
        }
        __syncthreads();

        #pragma unroll
        for (int kk = 0; kk < BK; kk++) {
            float af[TM], bf[TN];
            float4 a0 = *(const float4*)&As[kk][ty * TM + 0];
            float4 a1 = *(const float4*)&As[kk][ty * TM + 4];
            af[0]=a0.x; af[1]=a0.y; af[2]=a0.z; af[3]=a0.w;
            af[4]=a1.x; af[5]=a1.y; af[6]=a1.z; af[7]=a1.w;
            float4 b0 = *(const float4*)&Bs[kk][tx * TN];
            bf[0]=b0.x; bf[1]=b0.y; bf[2]=b0.z; bf[3]=b0.w;
            #pragma unroll
            for (int i = 0; i < TM; i++)
                #pragma unroll
                for (int j = 0; j < TN; j++)
                    acc[i][j] = fmaf(af[i], bf[j], acc[i][j]);
        }
        __syncthreads();
    }

    // Write back (+bias)
    #pragma unroll
    for (int i = 0; i < TM; i++) {
        const int row = row0 + ty * TM + i;
        const float bv = bias ? bias[row] : 0.f;
        float4 o;
        o.x = acc[i][0] + bv;
        o.y = acc[i][1] + bv;
        o.z = acc[i][2] + bv;
        o.w = acc[i][3] + bv;
        *(float4*)(Cbase + (long)row * N + col0 + tx * TN) = o;
    }
}

// ---------------------------------------------------------------------------
// Neighborhood attention: 3x3 window, softmax over 9 taps, zero-padded taps
// participate with logit 0 and v=0 (matches F.unfold zero padding).
// One thread per (b, head, y, x). qkv channel-major: (b, ch, y, x).
// ---------------------------------------------------------------------------
__global__ __launch_bounds__(64) void attn_kernel(
    const float* __restrict__ qkv, float* __restrict__ ao)
{
    const int x = threadIdx.x;
    if (x >= IMG_W) return;
    const int y = blockIdx.x;
    const int bh = blockIdx.y;
    const int head = bh & (HEADS - 1);
    const int b = bh >> 3;

    const float* q = qkv + ((long)b * QKV_CH + head * DHEAD) * HW;
    const float* k = q + (long)INNER * HW;
    const float* v = q + 2L * INNER * HW;
    const int p = y * IMG_W + x;

    // Tap offsets + validity (row-major over (dy,dx), matching unfold order)
    bool valid[9];
    int off[9];
    #pragma unroll
    for (int t = 0; t < 9; t++) {
        const int dy = t / 3 - 1;
        const int dx = t % 3 - 1;
        const int yy = y + dy;
        const int xx = x + dx;
        valid[t] = (yy >= 0) && (yy < IMG_H) && (xx >= 0) && (xx < IMG_W);
        off[t] = valid[t] ? (yy * IMG_W + xx) : 0;
    }

    float dots[9];
    #pragma unroll
    for (int t = 0; t < 9; t++) dots[t] = 0.f;

    #pragma unroll 4
    for (int d = 0; d < DHEAD; d++) {
        const long dp = (long)d * HW;
        const float qv = q[dp + p];
        #pragma unroll
        for (int t = 0; t < 9; t++) {
            const float kv = valid[t] ? k[dp + off[t]] : 0.f;
            dots[t] = fmaf(qv, kv, dots[t]);
        }
    }

    float m = -1e30f;
    #pragma unroll
    for (int t = 0; t < 9; t++) {
        dots[t] *= SCALE;          // invalid taps: 0*SCALE = 0 (padded-logit semantics)
        m = fmaxf(m, dots[t]);
    }
    float w[9];
    float s = 0.f;
    #pragma unroll
    for (int t = 0; t < 9; t++) {
        w[t] = __expf(dots[t] - m);
        s += w[t];
    }
    const float inv = 1.f / s;
    #pragma unroll
    for (int t = 0; t < 9; t++) w[t] *= inv;

    float* o = ao + ((long)b * INNER + head * DHEAD) * HW;
    #pragma unroll 4
    for (int d = 0; d < DHEAD; d++) {
        const long dp = (long)d * HW;
        float a = 0.f;
        #pragma unroll
        for (int t = 0; t < 9; t++) {
            const float vv = valid[t] ? v[dp + off[t]] : 0.f;
            a = fmaf(w[t], vv, a);
        }
        o[dp + p] = a;
    }
}

// ---------------------------------------------------------------------------
extern "C" void kernel_launch(void* const* d_in, const int* in_sizes, int n_in,
                              void* d_out, int out_size)
{
    const float* x   = (const float*)d_in[0];   // (4,384,56,56)
    const float* Wq  = (const float*)d_in[1];   // (512,384)
    const float* Wkv = (const float*)d_in[2];   // (1024,384)
    const float* Wo  = (const float*)d_in[3];   // (384,512)
    const float* bo  = (const float*)d_in[4];   // (384,)
    float* out = (float*)d_out;                 // (4,384,56,56)

    float* qkv; cudaGetSymbolAddress((void**)&qkv, g_qkv);
    float* ao;  cudaGetSymbolAddress((void**)&ao,  g_ao);

    // 1) fused q+kv projection: [1536x384] @ [384x3136] per batch
    {
        dim3 grid(HW / BN, QKV_CH / BM, BATCH);
        gemm_kernel<<<grid, 256>>>(Wq, Wkv, INNER, x, nullptr, qkv,
                                   QKV_CH, HW, DIM,
                                   (long)DIM * HW, (long)QKV_CH * HW);
    }

    // 2) neighborhood attention
    {
        dim3 grid(IMG_H, BATCH * HEADS);
        attn_kernel<<<grid, 64>>>(qkv, ao);
    }

    // 3) output projection + bias: [384x512] @ [512x3136] per batch
    {
        dim3 grid(HW / BN, DIM / BM, BATCH);
        gemm_kernel<<<grid, 256>>>(Wo, Wo, 1 << 30, ao, bo, out,
                                   DIM, HW, INNER,
                                   (long)INNER * HW, (long)DIM * HW);
    }
}

// round 5
// speedup vs baseline: 1.0968x; 1.0956x over previous
#include <cuda_runtime.h>
#include <cuda_bf16.h>
#include <cstdint>
#include <cstddef>

#define BATCH   4
#define DIMC    384
#define HEADS   8
#define DHEAD   64
#define INNER   512
#define QKV_CH  1536
#define IMG_H   56
#define IMG_W   56
#define HW      3136
#define NPIX    (BATCH * HW)      // 12544
#define SCALE   0.125f

#define K1P     1152              // 3*384
#define K2P     1536              // 3*512

// Scratch (device globals; allocation forbidden)
__device__ __nv_bfloat16 g_xT  [(size_t)NPIX * K1P];     // A-side [hi|lo|hi]
__device__ __nv_bfloat16 g_wqkv[(size_t)QKV_CH * K1P];   // B-side [hi|hi|lo]
__device__ __nv_bfloat16 g_wo  [(size_t)DIMC * K2P];     // A-side [hi|lo|hi]
__device__ float         g_qkvT[(size_t)NPIX * QKV_CH];  // pixel-major q|k|v
__device__ __nv_bfloat16 g_aoT [(size_t)NPIX * K2P];     // B-side [hi|hi|lo]

// ---------------- PTX helpers (baseline sm_80+ features only) ----------------
__device__ __forceinline__ uint32_t smem_u32(const void* p) {
    uint32_t a;
    asm("{ .reg .u64 t; cvta.to.shared.u64 t, %1; cvt.u32.u64 %0, t; }" : "=r"(a) : "l"(p));
    return a;
}
__device__ __forceinline__ void cp_async16(uint32_t saddr, const void* gptr) {
    asm volatile("cp.async.cg.shared.global [%0], [%1], 16;\n" :: "r"(saddr), "l"(gptr));
}
__device__ __forceinline__ void cp_commit() {
    asm volatile("cp.async.commit_group;\n" ::: "memory");
}
template <int N> __device__ __forceinline__ void cp_wait() {
    asm volatile("cp.async.wait_group %0;\n" :: "n"(N) : "memory");
}
__device__ __forceinline__ void ldsm_x4(uint32_t addr, uint32_t& r0, uint32_t& r1,
                                        uint32_t& r2, uint32_t& r3) {
    asm volatile("ldmatrix.sync.aligned.m8n8.x4.shared.b16 {%0,%1,%2,%3}, [%4];"
                 : "=r"(r0), "=r"(r1), "=r"(r2), "=r"(r3) : "r"(addr));
}
__device__ __forceinline__ void mma16816(float* d, const uint32_t* a, const uint32_t* b) {
    asm volatile("mma.sync.aligned.m16n8k16.row.col.f32.bf16.bf16.f32 "
        "{%0,%1,%2,%3}, {%4,%5,%6,%7}, {%8,%9}, {%0,%1,%2,%3};"
        : "+f"(d[0]), "+f"(d[1]), "+f"(d[2]), "+f"(d[3])
        : "r"(a[0]), "r"(a[1]), "r"(a[2]), "r"(a[3]), "r"(b[0]), "r"(b[1]));
}

// ---------------- input converts ----------------
__device__ __forceinline__ void split_bf16(float v, __nv_bfloat16& hi, __nv_bfloat16& lo) {
    hi = __float2bfloat16(v);
    lo = __float2bfloat16(v - __bfloat162float(hi));
}

__global__ __launch_bounds__(256) void transpose_convert(
    const float* __restrict__ x, __nv_bfloat16* __restrict__ xT)
{
    __shared__ float t[32][33];
    const int p0 = blockIdx.x * 32, c0 = blockIdx.y * 32, b = blockIdx.z;
    const int tx = threadIdx.x, ty = threadIdx.y;
    const float* src = x + (size_t)b * DIMC * HW;
    #pragma unroll
    for (int i = 0; i < 32; i += 8)
        t[ty + i][tx] = src[(size_t)(c0 + ty + i) * HW + p0 + tx];
    __syncthreads();
    __nv_bfloat16* dst = xT + (size_t)b * HW * K1P;
    #pragma unroll
    for (int i = 0; i < 32; i += 8) {
        const float v = t[tx][ty + i];
        __nv_bfloat16 hi, lo; split_bf16(v, hi, lo);
        const size_t row = (size_t)(p0 + ty + i) * K1P;
        dst[row + c0 + tx]       = hi;   // A-side: [hi | lo | hi]
        dst[row + 384 + c0 + tx] = lo;
        dst[row + 768 + c0 + tx] = hi;
    }
}

__global__ __launch_bounds__(384) void wqkv_convert(
    const float* __restrict__ Wq, const float* __restrict__ Wkv,
    __nv_bfloat16* __restrict__ out)
{
    const int row = blockIdx.x, k = threadIdx.x;
    const float w = (row < INNER) ? Wq[(size_t)row * DIMC + k]
                                  : Wkv[(size_t)(row - INNER) * DIMC + k];
    __nv_bfloat16 hi, lo; split_bf16(w, hi, lo);
    const size_t base = (size_t)row * K1P;
    out[base + k]       = hi;            // B-side: [hi | hi | lo]
    out[base + 384 + k] = hi;
    out[base + 768 + k] = lo;
}

__global__ __launch_bounds__(512) void wo_convert(
    const float* __restrict__ Wo, __nv_bfloat16* __restrict__ out)
{
    const int row = blockIdx.x, k = threadIdx.x;
    const float w = Wo[(size_t)row * INNER + k];
    __nv_bfloat16 hi, lo; split_bf16(w, hi, lo);
    const size_t base = (size_t)row * K2P;
    out[base + k]        = hi;           // A-side: [hi | lo | hi]
    out[base + 512 + k]  = lo;
    out[base + 1024 + k] = hi;
}

// ---------------- mma.sync bf16 GEMM ----------------
// D[m][n] = sum_k A[m][k]*B[n][k]; CTA tile 128x128, K-chunk 64, 3-stage cp.async.
// 8 warps as 2(M) x 4(N); warp tile 64x32 = 4x4 m16n8k16 fragments.
#define STG 32768   // per stage: A 128*128B + B 128*128B

__device__ __forceinline__ void stage_ld(uint32_t sA, uint32_t sB,
    const __nv_bfloat16* __restrict__ Ag, int lda,
    const __nv_bfloat16* __restrict__ Bg, int ldb, int kt, int tid)
{
    #pragma unroll
    for (int i = 0; i < 4; i++) {
        const int idx = tid + i * 256;
        const int row = idx >> 3, j = idx & 7;
        const uint32_t off = (uint32_t)(row * 128 + ((j ^ (row & 7)) * 16));
        cp_async16(sA + off, Ag + (size_t)row * lda + kt + j * 8);
    }
    #pragma unroll
    for (int i = 0; i < 4; i++) {
        const int idx = tid + i * 256;
        const int row = idx >> 3, j = idx & 7;
        const uint32_t off = (uint32_t)(row * 128 + ((j ^ (row & 7)) * 16));
        cp_async16(sB + off, Bg + (size_t)row * ldb + kt + j * 8);
    }
}

template <int T, int EPI>
__global__ __launch_bounds__(256) void hmma_gemm(
    const __nv_bfloat16* __restrict__ A, int lda,
    const __nv_bfloat16* __restrict__ B, int ldb,
    const float* __restrict__ bias, float* __restrict__ C, int ldc)
{
    extern __shared__ char dynraw[];
    const uint32_t smem = smem_u32(dynraw);
    const int tid = threadIdx.x;
    const int w = tid >> 5, l = tid & 31;
    const int wm = w >> 2, wn = w & 3;
    const int n0 = blockIdx.x * 128, m0 = blockIdx.y * 128;

    const __nv_bfloat16* Ag = A + (size_t)m0 * lda;
    const __nv_bfloat16* Bg = B + (size_t)n0 * ldb;

    float acc[4][4][4];
    #pragma unroll
    for (int i = 0; i < 4; i++)
        #pragma unroll
        for (int j = 0; j < 4; j++)
            #pragma unroll
            for (int c = 0; c < 4; c++) acc[i][j][c] = 0.f;

    // ldmatrix lane constants (all non-trans; K-major operands)
    // A matrices: m0=(rows0-7,k0-7) m1=(rows8-15,k0-7) m2=(rows0-7,k8-15) m3=(rows8-15,k8-15)
    const int arow_l = (l & 7) + ((l >> 3) & 1) * 8;   // A: row-in-16
    const int acol_l = (l >> 4) & 1;                   // A: k-half chunk
    // B matrices: m0=(n0-7,k0-7) m1=(n0-7,k8-15) m2=(n8-15,k0-7) m3=(n8-15,k8-15)
    const int brow_l = (l & 7) + ((l >> 4) & 1) * 8;   // B: n-row-in-16
    const int bcol_l = (l >> 3) & 1;                   // B: k-half chunk

    int abase[4], asw[4];
    #pragma unroll
    for (int i = 0; i < 4; i++) {
        const int mrow = wm * 64 + i * 16 + arow_l;
        abase[i] = mrow * 128;
        asw[i]   = mrow & 7;
    }
    int bbase[2], bsw[2];
    #pragma unroll
    for (int jj = 0; jj < 2; jj++) {
        const int nrow = wn * 32 + jj * 16 + brow_l;
        bbase[jj] = nrow * 128;
        bsw[jj]   = nrow & 7;
    }

    // Prologue: stages 0, 1
    stage_ld(smem,       smem + 16384,       Ag, lda, Bg, ldb, 0,  tid); cp_commit();
    stage_ld(smem + STG, smem + STG + 16384, Ag, lda, Bg, ldb, 64, tid); cp_commit();

    #pragma unroll 1
    for (int t = 0; t < T; t++) {
        cp_wait<1>();
        __syncthreads();
        if (t + 2 < T) {
            const int s2 = (t + 2) % 3;
            stage_ld(smem + s2 * STG, smem + s2 * STG + 16384,
                     Ag, lda, Bg, ldb, (t + 2) * 64, tid);
        }
        cp_commit();

        const uint32_t sA = smem + (t % 3) * STG;
        const uint32_t sB = sA + 16384;
        #pragma unroll
        for (int ks = 0; ks < 4; ks++) {
            uint32_t af[4][4];
            #pragma unroll
            for (int i = 0; i < 4; i++)
                ldsm_x4(sA + abase[i] + (((ks * 2 + acol_l) ^ asw[i]) * 16),
                        af[i][0], af[i][1], af[i][2], af[i][3]);
            uint32_t bf[4][2];
            #pragma unroll
            for (int jj = 0; jj < 2; jj++)
                ldsm_x4(sB + bbase[jj] + (((ks * 2 + bcol_l) ^ bsw[jj]) * 16),
                        bf[jj * 2][0], bf[jj * 2][1], bf[jj * 2 + 1][0], bf[jj * 2 + 1][1]);
            #pragma unroll
            for (int i = 0; i < 4; i++)
                #pragma unroll
                for (int j = 0; j < 4; j++)
                    mma16816(acc[i][j], af[i], bf[j]);
        }
    }

    // Epilogue: lane l holds rows (l>>2) and (l>>2)+8, cols 2*(l&3)
    const int r4 = l >> 2;
    const int c2 = (l & 3) * 2;
    #pragma unroll
    for (int i = 0; i < 4; i++) {
        const int row_a = m0 + wm * 64 + i * 16 + r4;
        #pragma unroll
        for (int h = 0; h < 2; h++) {
            const int row = row_a + h * 8;
            #pragma unroll
            for (int j = 0; j < 4; j++) {
                const int col = n0 + wn * 32 + j * 8 + c2;
                float2 v = make_float2(acc[i][j][h * 2], acc[i][j][h * 2 + 1]);
                if (EPI == 0) {
                    *(float2*)(C + (size_t)row * ldc + col) = v;
                } else {
                    const float bv = bias[row];
                    const int bb = col / HW;
                    const int hw = col - bb * HW;
                    v.x += bv; v.y += bv;
                    *(float2*)(C + ((size_t)bb * DIMC + row) * HW + hw) = v;
                }
            }
        }
    }
}

// ---------------- attention (pixel-major) ----------------
#define SQ_STRIDE 57
#define SK_STRIDE 59
#define SQ_FLOATS (64 * SQ_STRIDE)
#define SK_FLOATS (3 * 64 * SK_STRIDE)
#define ATTN_SMEM ((SQ_FLOATS + 2 * SK_FLOATS) * 4)

__global__ __launch_bounds__(64) void attn_kernel(
    const float* __restrict__ qkvT, __nv_bfloat16* __restrict__ aoT)
{
    extern __shared__ float sm[];
    float* sq = sm;
    float* sk = sm + SQ_FLOATS;
    float* sv = sk + SK_FLOATS;

    const int tid = threadIdx.x;
    const int y = blockIdx.x;
    const int head = blockIdx.y & (HEADS - 1);
    const int b = blockIdx.y >> 3;
    const float* base = qkvT + (size_t)b * HW * QKV_CH;

    for (int idx = tid; idx < IMG_W * 16; idx += 64) {
        const int px = idx >> 4, c = idx & 15;
        const float4 qv = *(const float4*)(base + (size_t)(y * IMG_W + px) * QKV_CH
                                           + head * DHEAD + c * 4);
        const int o = (c * 4) * SQ_STRIDE + px;
        sq[o] = qv.x; sq[o + SQ_STRIDE] = qv.y;
        sq[o + 2 * SQ_STRIDE] = qv.z; sq[o + 3 * SQ_STRIDE] = qv.w;
    }
    for (int idx = tid; idx < 3 * 58 * 16; idx += 64) {
        const int r = idx / (58 * 16);
        const int rem = idx - r * (58 * 16);
        const int px = rem >> 4, c = rem & 15;
        const int yy = y + r - 1, xx = px - 1;
        float4 kv = make_float4(0.f, 0.f, 0.f, 0.f), vv = kv;
        if (yy >= 0 && yy < IMG_H && xx >= 0 && xx < IMG_W) {
            const float* pb = base + (size_t)(yy * IMG_W + xx) * QKV_CH + head * DHEAD + c * 4;
            kv = *(const float4*)(pb + INNER);
            vv = *(const float4*)(pb + 2 * INNER);
        }
        const int o = (r * 64 + c * 4) * SK_STRIDE + px;
        sk[o] = kv.x; sk[o + SK_STRIDE] = kv.y;
        sk[o + 2 * SK_STRIDE] = kv.z; sk[o + 3 * SK_STRIDE] = kv.w;
        sv[o] = vv.x; sv[o + SK_STRIDE] = vv.y;
        sv[o + 2 * SK_STRIDE] = vv.z; sv[o + 3 * SK_STRIDE] = vv.w;
    }
    __syncthreads();
    if (tid >= IMG_W) return;
    const int x = tid;

    float dots[9];
    #pragma unroll
    for (int t = 0; t < 9; t++) dots[t] = 0.f;
    #pragma unroll
    for (int c = 0; c < 16; c++) {
        const int qo = (c * 4) * SQ_STRIDE + x;
        const float q0 = sq[qo], q1 = sq[qo + SQ_STRIDE];
        const float q2 = sq[qo + 2 * SQ_STRIDE], q3 = sq[qo + 3 * SQ_STRIDE];
        #pragma unroll
        for (int t = 0; t < 9; t++) {
            const int o = ((t / 3) * 64 + c * 4) * SK_STRIDE + x + (t % 3);
            dots[t] = fmaf(q0, sk[o], dots[t]);
            dots[t] = fmaf(q1, sk[o + SK_STRIDE], dots[t]);
            dots[t] = fmaf(q2, sk[o + 2 * SK_STRIDE], dots[t]);
            dots[t] = fmaf(q3, sk[o + 3 * SK_STRIDE], dots[t]);
        }
    }
    float m = -1e30f;
    #pragma unroll
    for (int t = 0; t < 9; t++) { dots[t] *= SCALE; m = fmaxf(m, dots[t]); }
    float w[9], s = 0.f;
    #pragma unroll
    for (int t = 0; t < 9; t++) { w[t] = __expf(dots[t] - m); s += w[t]; }
    const float inv = 1.f / s;
    #pragma unroll
    for (int t = 0; t < 9; t++) w[t] *= inv;

    float o[DHEAD];
    #pragma unroll
    for (int d = 0; d < DHEAD; d++) o[d] = 0.f;
    #pragma unroll
    for (int c = 0; c < 16; c++) {
        #pragma unroll
        for (int t = 0; t < 9; t++) {
            const int ob = ((t / 3) * 64 + c * 4) * SK_STRIDE + x + (t % 3);
            o[c * 4 + 0] = fmaf(w[t], sv[ob], o[c * 4 + 0]);
            o[c * 4 + 1] = fmaf(w[t], sv[ob + SK_STRIDE], o[c * 4 + 1]);
            o[c * 4 + 2] = fmaf(w[t], sv[ob + 2 * SK_STRIDE], o[c * 4 + 2]);
            o[c * 4 + 3] = fmaf(w[t], sv[ob + 3 * SK_STRIDE], o[c * 4 + 3]);
        }
    }

    __nv_bfloat16* dst = aoT + (size_t)(b * HW + y * IMG_W + x) * K2P;
    const int chb = head * DHEAD;
    #pragma unroll
    for (int c = 0; c < 64; c += 2) {
        __nv_bfloat16 h0, l0, h1, l1;
        split_bf16(o[c], h0, l0);
        split_bf16(o[c + 1], h1, l1);
        __nv_bfloat162 hi2; hi2.x = h0; hi2.y = h1;
        __nv_bfloat162 lo2; lo2.x = l0; lo2.y = l1;
        *(__nv_bfloat162*)(dst + chb + c)        = hi2;  // B-side: [hi | hi | lo]
        *(__nv_bfloat162*)(dst + 512 + chb + c)  = hi2;
        *(__nv_bfloat162*)(dst + 1024 + chb + c) = lo2;
    }
}

// ---------------- launch ----------------
extern "C" void kernel_launch(void* const* d_in, const int* in_sizes, int n_in,
                              void* d_out, int out_size)
{
    const float* x   = (const float*)d_in[0];
    const float* Wq  = (const float*)d_in[1];
    const float* Wkv = (const float*)d_in[2];
    const float* Wo  = (const float*)d_in[3];
    const float* bo  = (const float*)d_in[4];
    float* out = (float*)d_out;

    __nv_bfloat16 *xT, *wqkv, *wo, *aoT;
    float* qkvT;
    cudaGetSymbolAddress((void**)&xT,   g_xT);
    cudaGetSymbolAddress((void**)&wqkv, g_wqkv);
    cudaGetSymbolAddress((void**)&wo,   g_wo);
    cudaGetSymbolAddress((void**)&qkvT, g_qkvT);
    cudaGetSymbolAddress((void**)&aoT,  g_aoT);

    const int gemm_smem = 3 * STG;   // 96 KB
    cudaFuncSetAttribute(hmma_gemm<K1P / 64, 0>,
                         cudaFuncAttributeMaxDynamicSharedMemorySize, gemm_smem);
    cudaFuncSetAttribute(hmma_gemm<K2P / 64, 1>,
                         cudaFuncAttributeMaxDynamicSharedMemorySize, gemm_smem);
    cudaFuncSetAttribute(attn_kernel,
                         cudaFuncAttributeMaxDynamicSharedMemorySize, ATTN_SMEM);

    // 0) converts
    transpose_convert<<<dim3(HW / 32, DIMC / 32, BATCH), dim3(32, 8)>>>(x, xT);
    wqkv_convert<<<QKV_CH, DIMC>>>(Wq, Wkv, wqkv);
    wo_convert<<<DIMC, INNER>>>(Wo, wo);

    // 1) qkv projection: D[p][ch], M=12544, N=1536, K'=1152
    hmma_gemm<K1P / 64, 0><<<dim3(QKV_CH / 128, NPIX / 128), 256, gemm_smem>>>(
        xT, K1P, wqkv, K1P, nullptr, qkvT, QKV_CH);

    // 2) neighborhood attention
    attn_kernel<<<dim3(IMG_H, BATCH * HEADS), 64, ATTN_SMEM>>>(qkvT, aoT);

    // 3) out projection: D[ch][p] -> out (channel-major) + bias, M=384, N=12544, K'=1536
    hmma_gemm<K2P / 64, 1><<<dim3(NPIX / 128, DIMC / 128), 256, gemm_smem>>>(
        wo, K2P, aoT, K2P, bo, out, 0);
}

// round 6
// speedup vs baseline: 2.4999x; 2.2793x over previous
#include <cuda_runtime.h>
#include <cuda_bf16.h>
#include <cstdint>
#include <cstddef>

#define BATCH   4
#define DIMC    384
#define HEADS   8
#define DHEAD   64
#define INNER   512
#define QKV_CH  1536
#define IMG_H   56
#define IMG_W   56
#define HW      3136
#define NPIX    (BATCH * HW)      // 12544
#define SCALE   0.125f

#define K1P     1152              // 3*384
#define K2P     1536              // 3*512

// Scratch (device globals; allocation forbidden)
__device__ __nv_bfloat16 g_xT  [(size_t)NPIX * K1P];     // A-side [hi|lo|hi]
__device__ __nv_bfloat16 g_wqkv[(size_t)QKV_CH * K1P];   // B-side [hi|hi|lo]
__device__ __nv_bfloat16 g_wo  [(size_t)DIMC * K2P];     // A-side [hi|lo|hi]
__device__ float         g_qkvT[(size_t)NPIX * QKV_CH];  // pixel-major q|k|v
__device__ __nv_bfloat16 g_aoT [(size_t)NPIX * K2P];     // B-side [hi|hi|lo]

// ---------------- PTX helpers (baseline sm_80+ features only) ----------------
__device__ __forceinline__ uint32_t smem_u32(const void* p) {
    uint32_t a;
    asm("{ .reg .u64 t; cvta.to.shared.u64 t, %1; cvt.u32.u64 %0, t; }" : "=r"(a) : "l"(p));
    return a;
}
__device__ __forceinline__ void cp_async16(uint32_t saddr, const void* gptr) {
    asm volatile("cp.async.cg.shared.global [%0], [%1], 16;\n" :: "r"(saddr), "l"(gptr));
}
__device__ __forceinline__ void cp_commit() {
    asm volatile("cp.async.commit_group;\n" ::: "memory");
}
template <int N> __device__ __forceinline__ void cp_wait() {
    asm volatile("cp.async.wait_group %0;\n" :: "n"(N) : "memory");
}
__device__ __forceinline__ void ldsm_x4(uint32_t addr, uint32_t& r0, uint32_t& r1,
                                        uint32_t& r2, uint32_t& r3) {
    asm volatile("ldmatrix.sync.aligned.m8n8.x4.shared.b16 {%0,%1,%2,%3}, [%4];"
                 : "=r"(r0), "=r"(r1), "=r"(r2), "=r"(r3) : "r"(addr));
}
__device__ __forceinline__ void mma16816(float* d, const uint32_t* a, const uint32_t* b) {
    asm volatile("mma.sync.aligned.m16n8k16.row.col.f32.bf16.bf16.f32 "
        "{%0,%1,%2,%3}, {%4,%5,%6,%7}, {%8,%9}, {%0,%1,%2,%3};"
        : "+f"(d[0]), "+f"(d[1]), "+f"(d[2]), "+f"(d[3])
        : "r"(a[0]), "r"(a[1]), "r"(a[2]), "r"(a[3]), "r"(b[0]), "r"(b[1]));
}

// ---------------- input converts ----------------
__device__ __forceinline__ void split_bf16(float v, __nv_bfloat16& hi, __nv_bfloat16& lo) {
    hi = __float2bfloat16(v);
    lo = __float2bfloat16(v - __bfloat162float(hi));
}

__global__ __launch_bounds__(256) void transpose_convert(
    const float* __restrict__ x, __nv_bfloat16* __restrict__ xT)
{
    __shared__ float t[32][33];
    const int p0 = blockIdx.x * 32, c0 = blockIdx.y * 32, b = blockIdx.z;
    const int tx = threadIdx.x, ty = threadIdx.y;
    const float* src = x + (size_t)b * DIMC * HW;
    #pragma unroll
    for (int i = 0; i < 32; i += 8)
        t[ty + i][tx] = src[(size_t)(c0 + ty + i) * HW + p0 + tx];
    __syncthreads();
    __nv_bfloat16* dst = xT + (size_t)b * HW * K1P;
    #pragma unroll
    for (int i = 0; i < 32; i += 8) {
        const float v = t[tx][ty + i];
        __nv_bfloat16 hi, lo; split_bf16(v, hi, lo);
        const size_t row = (size_t)(p0 + ty + i) * K1P;
        dst[row + c0 + tx]       = hi;   // A-side: [hi | lo | hi]
        dst[row + 384 + c0 + tx] = lo;
        dst[row + 768 + c0 + tx] = hi;
    }
}

__global__ __launch_bounds__(384) void wqkv_convert(
    const float* __restrict__ Wq, const float* __restrict__ Wkv,
    __nv_bfloat16* __restrict__ out)
{
    const int row = blockIdx.x, k = threadIdx.x;
    const float w = (row < INNER) ? Wq[(size_t)row * DIMC + k]
                                  : Wkv[(size_t)(row - INNER) * DIMC + k];
    __nv_bfloat16 hi, lo; split_bf16(w, hi, lo);
    const size_t base = (size_t)row * K1P;
    out[base + k]       = hi;            // B-side: [hi | hi | lo]
    out[base + 384 + k] = hi;
    out[base + 768 + k] = lo;
}

__global__ __launch_bounds__(512) void wo_convert(
    const float* __restrict__ Wo, __nv_bfloat16* __restrict__ out)
{
    const int row = blockIdx.x, k = threadIdx.x;
    const float w = Wo[(size_t)row * INNER + k];
    __nv_bfloat16 hi, lo; split_bf16(w, hi, lo);
    const size_t base = (size_t)row * K2P;
    out[base + k]        = hi;           // A-side: [hi | lo | hi]
    out[base + 512 + k]  = lo;
    out[base + 1024 + k] = hi;
}

// ---------------- mma.sync bf16 GEMM ----------------
// D[m][n] = sum_k A[m][k]*B[n][k]; CTA tile 128x256, K-chunk 64, 3-stage cp.async.
// 8 warps as 2(M) x 4(N); warp tile 64x64 = 4x8 m16n8k16 fragments.
#define STG 49152   // per stage: A 128*128B (16KB) + B 256*128B (32KB)

__device__ __forceinline__ void stage_ld(uint32_t sA, uint32_t sB,
    const __nv_bfloat16* __restrict__ Ag, int lda,
    const __nv_bfloat16* __restrict__ Bg, int ldb, int kt, int tid)
{
    #pragma unroll
    for (int i = 0; i < 4; i++) {
        const int idx = tid + i * 256;
        const int row = idx >> 3, j = idx & 7;
        const uint32_t off = (uint32_t)(row * 128 + ((j ^ (row & 7)) * 16));
        cp_async16(sA + off, Ag + (size_t)row * lda + kt + j * 8);
    }
    #pragma unroll
    for (int i = 0; i < 8; i++) {
        const int idx = tid + i * 256;
        const int row = idx >> 3, j = idx & 7;
        const uint32_t off = (uint32_t)(row * 128 + ((j ^ (row & 7)) * 16));
        cp_async16(sB + off, Bg + (size_t)row * ldb + kt + j * 8);
    }
}

template <int T, int EPI>
__global__ __launch_bounds__(256) void hmma_gemm(
    const __nv_bfloat16* __restrict__ A, int lda,
    const __nv_bfloat16* __restrict__ B, int ldb,
    const float* __restrict__ bias, float* __restrict__ C, int ldc)
{
    extern __shared__ char dynraw[];
    const uint32_t smem = smem_u32(dynraw);
    const int tid = threadIdx.x;
    const int w = tid >> 5, l = tid & 31;
    const int wm = w >> 2, wn = w & 3;
    const int n0 = blockIdx.x * 256, m0 = blockIdx.y * 128;

    const __nv_bfloat16* Ag = A + (size_t)m0 * lda;
    const __nv_bfloat16* Bg = B + (size_t)n0 * ldb;

    float acc[4][8][4];
    #pragma unroll
    for (int i = 0; i < 4; i++)
        #pragma unroll
        for (int j = 0; j < 8; j++)
            #pragma unroll
            for (int c = 0; c < 4; c++) acc[i][j][c] = 0.f;

    // ldmatrix lane constants (all non-trans; K-major operands)
    const int arow_l = (l & 7) + ((l >> 3) & 1) * 8;   // A: row-in-16
    const int acol_l = (l >> 4) & 1;                   // A: k-half chunk
    const int brow_l = (l & 7) + ((l >> 4) & 1) * 8;   // B: n-row-in-16
    const int bcol_l = (l >> 3) & 1;                   // B: k-half chunk

    int abase[4], asw[4];
    #pragma unroll
    for (int i = 0; i < 4; i++) {
        const int mrow = wm * 64 + i * 16 + arow_l;
        abase[i] = mrow * 128;
        asw[i]   = mrow & 7;
    }
    int bbase[4], bsw[4];
    #pragma unroll
    for (int jj = 0; jj < 4; jj++) {
        const int nrow = wn * 64 + jj * 16 + brow_l;
        bbase[jj] = nrow * 128;
        bsw[jj]   = nrow & 7;
    }

    // Prologue: stages 0, 1
    stage_ld(smem,       smem + 16384,       Ag, lda, Bg, ldb, 0,  tid); cp_commit();
    stage_ld(smem + STG, smem + STG + 16384, Ag, lda, Bg, ldb, 64, tid); cp_commit();

    #pragma unroll 1
    for (int t = 0; t < T; t++) {
        cp_wait<1>();
        __syncthreads();
        if (t + 2 < T) {
            const int s2 = (t + 2) % 3;
            stage_ld(smem + s2 * STG, smem + s2 * STG + 16384,
                     Ag, lda, Bg, ldb, (t + 2) * 64, tid);
        }
        cp_commit();

        const uint32_t sA = smem + (t % 3) * STG;
        const uint32_t sB = sA + 16384;
        #pragma unroll
        for (int ks = 0; ks < 4; ks++) {
            uint32_t af[4][4];
            #pragma unroll
            for (int i = 0; i < 4; i++)
                ldsm_x4(sA + abase[i] + (((ks * 2 + acol_l) ^ asw[i]) * 16),
                        af[i][0], af[i][1], af[i][2], af[i][3]);
            uint32_t bf[8][2];
            #pragma unroll
            for (int jj = 0; jj < 4; jj++)
                ldsm_x4(sB + bbase[jj] + (((ks * 2 + bcol_l) ^ bsw[jj]) * 16),
                        bf[jj * 2][0], bf[jj * 2][1], bf[jj * 2 + 1][0], bf[jj * 2 + 1][1]);
            #pragma unroll
            for (int i = 0; i < 4; i++)
                #pragma unroll
                for (int j = 0; j < 8; j++)
                    mma16816(acc[i][j], af[i], bf[j]);
        }
    }

    // Epilogue: lane l holds rows (l>>2) and (l>>2)+8, cols 2*(l&3)
    const int r4 = l >> 2;
    const int c2 = (l & 3) * 2;
    #pragma unroll
    for (int i = 0; i < 4; i++) {
        const int row_a = m0 + wm * 64 + i * 16 + r4;
        #pragma unroll
        for (int h = 0; h < 2; h++) {
            const int row = row_a + h * 8;
            #pragma unroll
            for (int j = 0; j < 8; j++) {
                const int col = n0 + wn * 64 + j * 8 + c2;
                float2 v = make_float2(acc[i][j][h * 2], acc[i][j][h * 2 + 1]);
                if (EPI == 0) {
                    *(float2*)(C + (size_t)row * ldc + col) = v;
                } else {
                    const float bv = bias[row];
                    const int bb = col / HW;
                    const int hw = col - bb * HW;
                    v.x += bv; v.y += bv;
                    *(float2*)(C + ((size_t)bb * DIMC + row) * HW + hw) = v;
                }
            }
        }
    }
}

// ---------------- attention: warp per (pixel, head), no smem ----------------
// Lane owns d = 2*lane, 2*lane+1. Padded taps -> dot 0 (unfold semantics).
// grid: (7 x-groups, IMG_H, BATCH*HEADS); 256 threads = 8 warps = 8 adjacent x.
__global__ __launch_bounds__(256) void attn_kernel(
    const float* __restrict__ qkvT, __nv_bfloat16* __restrict__ aoT)
{
    const int l  = threadIdx.x & 31;
    const int x  = blockIdx.x * 8 + (threadIdx.x >> 5);
    const int y  = blockIdx.y;
    const int head = blockIdx.z & (HEADS - 1);
    const int b    = blockIdx.z >> 3;

    const size_t pbase = (size_t)(b * HW + y * IMG_W + x) * QKV_CH;
    const int chb = head * DHEAD + l * 2;

    const float2 q = *(const float2*)(qkvT + pbase + chb);

    float dots[9];
    #pragma unroll
    for (int t = 0; t < 9; t++) {
        const int yy = y + t / 3 - 1;
        const int xx = x + t % 3 - 1;
        float d = 0.f;
        if (yy >= 0 && yy < IMG_H && xx >= 0 && xx < IMG_W) {
            const float2 kk = *(const float2*)(
                qkvT + (size_t)(b * HW + yy * IMG_W + xx) * QKV_CH + INNER + chb);
            d = fmaf(q.x, kk.x, q.y * kk.y);
        }
        dots[t] = d;
    }
    // butterfly reduce each tap over the warp (all lanes end with full dot)
    #pragma unroll
    for (int off = 16; off; off >>= 1)
        #pragma unroll
        for (int t = 0; t < 9; t++)
            dots[t] += __shfl_xor_sync(0xFFFFFFFFu, dots[t], off);

    float m = -1e30f;
    #pragma unroll
    for (int t = 0; t < 9; t++) { dots[t] *= SCALE; m = fmaxf(m, dots[t]); }
    float wgt[9], s = 0.f;
    #pragma unroll
    for (int t = 0; t < 9; t++) { wgt[t] = __expf(dots[t] - m); s += wgt[t]; }
    const float inv = 1.f / s;

    float2 o = make_float2(0.f, 0.f);
    #pragma unroll
    for (int t = 0; t < 9; t++) {
        const int yy = y + t / 3 - 1;
        const int xx = x + t % 3 - 1;
        if (yy >= 0 && yy < IMG_H && xx >= 0 && xx < IMG_W) {
            const float2 vv = *(const float2*)(
                qkvT + (size_t)(b * HW + yy * IMG_W + xx) * QKV_CH + 2 * INNER + chb);
            const float wt = wgt[t] * inv;
            o.x = fmaf(wt, vv.x, o.x);
            o.y = fmaf(wt, vv.y, o.y);
        }
    }

    __nv_bfloat16 h0, l0, h1, l1;
    split_bf16(o.x, h0, l0);
    split_bf16(o.y, h1, l1);
    __nv_bfloat162 hi2; hi2.x = h0; hi2.y = h1;
    __nv_bfloat162 lo2; lo2.x = l0; lo2.y = l1;
    __nv_bfloat16* dst = g_aoT + (size_t)(b * HW + y * IMG_W + x) * K2P + chb;
    *(__nv_bfloat162*)(dst)        = hi2;   // B-side: [hi | hi | lo]
    *(__nv_bfloat162*)(dst + 512)  = hi2;
    *(__nv_bfloat162*)(dst + 1024) = lo2;
    (void)aoT;
}

// ---------------- launch ----------------
extern "C" void kernel_launch(void* const* d_in, const int* in_sizes, int n_in,
                              void* d_out, int out_size)
{
    const float* x   = (const float*)d_in[0];
    const float* Wq  = (const float*)d_in[1];
    const float* Wkv = (const float*)d_in[2];
    const float* Wo  = (const float*)d_in[3];
    const float* bo  = (const float*)d_in[4];
    float* out = (float*)d_out;

    __nv_bfloat16 *xT, *wqkv, *wo, *aoT;
    float* qkvT;
    cudaGetSymbolAddress((void**)&xT,   g_xT);
    cudaGetSymbolAddress((void**)&wqkv, g_wqkv);
    cudaGetSymbolAddress((void**)&wo,   g_wo);
    cudaGetSymbolAddress((void**)&qkvT, g_qkvT);
    cudaGetSymbolAddress((void**)&aoT,  g_aoT);

    const int gemm_smem = 3 * STG;   // 144 KB
    cudaFuncSetAttribute(hmma_gemm<K1P / 64, 0>,
                         cudaFuncAttributeMaxDynamicSharedMemorySize, gemm_smem);
    cudaFuncSetAttribute(hmma_gemm<K2P / 64, 1>,
                         cudaFuncAttributeMaxDynamicSharedMemorySize, gemm_smem);

    // 0) converts
    transpose_convert<<<dim3(HW / 32, DIMC / 32, BATCH), dim3(32, 8)>>>(x, xT);
    wqkv_convert<<<QKV_CH, DIMC>>>(Wq, Wkv, wqkv);
    wo_convert<<<DIMC, INNER>>>(Wo, wo);

    // 1) qkv projection: D[p][ch], M=12544, N=1536, K'=1152
    hmma_gemm<K1P / 64, 0><<<dim3(QKV_CH / 256, NPIX / 128), 256, gemm_smem>>>(
        xT, K1P, wqkv, K1P, nullptr, qkvT, QKV_CH);

    // 2) neighborhood attention (warp per pixel-head)
    attn_kernel<<<dim3(IMG_W / 8, IMG_H, BATCH * HEADS), 256>>>(qkvT, aoT);

    // 3) out projection: D[ch][p] -> out (channel-major) + bias, M=384, N=12544, K'=1536
    hmma_gemm<K2P / 64, 1><<<dim3(NPIX / 256, DIMC / 128), 256, gemm_smem>>>(
        wo, K2P, aoT, K2P, bo, out, 0);
}

// round 7
// speedup vs baseline: 3.2326x; 1.2931x over previous
#include <cuda_runtime.h>
#include <cuda_fp16.h>
#include <cstdint>
#include <cstddef>

#define BATCH   4
#define DIMC    384
#define HEADS   8
#define DHEAD   64
#define INNER   512
#define QKV_CH  1536
#define IMG_H   56
#define IMG_W   56
#define HW      3136
#define NPIX    (BATCH * HW)      // 12544
#define SCALE   0.125f

#define K1P     768               // 2*384 (fp16 [hi|lo] x [hi|hi])
#define K2P     1024              // 2*512

// Scratch (device globals; allocation forbidden)
__device__ __half g_xT  [(size_t)NPIX * K1P];     // A-side [hi|lo]
__device__ __half g_wqkv[(size_t)QKV_CH * K1P];   // B-side [hi|hi]
__device__ __half g_wo  [(size_t)DIMC * K2P];     // A-side [hi|lo]
__device__ float  g_qkvT[(size_t)NPIX * QKV_CH];  // pixel-major q|k|v
__device__ __half g_aoT [(size_t)NPIX * K2P];     // B-side [hi|hi]

// ---------------- PTX helpers (baseline sm_80+ features only) ----------------
__device__ __forceinline__ uint32_t smem_u32(const void* p) {
    uint32_t a;
    asm("{ .reg .u64 t; cvta.to.shared.u64 t, %1; cvt.u32.u64 %0, t; }" : "=r"(a) : "l"(p));
    return a;
}
__device__ __forceinline__ void cp_async16(uint32_t saddr, const void* gptr) {
    asm volatile("cp.async.cg.shared.global [%0], [%1], 16;\n" :: "r"(saddr), "l"(gptr));
}
__device__ __forceinline__ void cp_commit() {
    asm volatile("cp.async.commit_group;\n" ::: "memory");
}
template <int N> __device__ __forceinline__ void cp_wait() {
    asm volatile("cp.async.wait_group %0;\n" :: "n"(N) : "memory");
}
__device__ __forceinline__ void ldsm_x4(uint32_t addr, uint32_t& r0, uint32_t& r1,
                                        uint32_t& r2, uint32_t& r3) {
    asm volatile("ldmatrix.sync.aligned.m8n8.x4.shared.b16 {%0,%1,%2,%3}, [%4];"
                 : "=r"(r0), "=r"(r1), "=r"(r2), "=r"(r3) : "r"(addr));
}
__device__ __forceinline__ void mma16816(float* d, const uint32_t* a, const uint32_t* b) {
    asm volatile("mma.sync.aligned.m16n8k16.row.col.f32.f16.f16.f32 "
        "{%0,%1,%2,%3}, {%4,%5,%6,%7}, {%8,%9}, {%0,%1,%2,%3};"
        : "+f"(d[0]), "+f"(d[1]), "+f"(d[2]), "+f"(d[3])
        : "r"(a[0]), "r"(a[1]), "r"(a[2]), "r"(a[3]), "r"(b[0]), "r"(b[1]));
}

// ---------------- input converts ----------------
__device__ __forceinline__ void split_f16(float v, __half& hi, __half& lo) {
    hi = __float2half(v);
    lo = __float2half(v - __half2float(hi));
}

__global__ __launch_bounds__(256) void transpose_convert(
    const float* __restrict__ x, __half* __restrict__ xT)
{
    __shared__ float t[32][33];
    const int p0 = blockIdx.x * 32, c0 = blockIdx.y * 32, b = blockIdx.z;
    const int tx = threadIdx.x, ty = threadIdx.y;
    const float* src = x + (size_t)b * DIMC * HW;
    #pragma unroll
    for (int i = 0; i < 32; i += 8)
        t[ty + i][tx] = src[(size_t)(c0 + ty + i) * HW + p0 + tx];
    __syncthreads();
    __half* dst = xT + (size_t)b * HW * K1P;
    #pragma unroll
    for (int i = 0; i < 32; i += 8) {
        const float v = t[tx][ty + i];
        __half hi, lo; split_f16(v, hi, lo);
        const size_t row = (size_t)(p0 + ty + i) * K1P;
        dst[row + c0 + tx]       = hi;   // A-side: [hi | lo]
        dst[row + 384 + c0 + tx] = lo;
    }
}

__global__ __launch_bounds__(384) void wqkv_convert(
    const float* __restrict__ Wq, const float* __restrict__ Wkv,
    __half* __restrict__ out)
{
    const int row = blockIdx.x, k = threadIdx.x;
    const float w = (row < INNER) ? Wq[(size_t)row * DIMC + k]
                                  : Wkv[(size_t)(row - INNER) * DIMC + k];
    const __half hi = __float2half(w);
    const size_t base = (size_t)row * K1P;
    out[base + k]       = hi;            // B-side: [hi | hi]
    out[base + 384 + k] = hi;
}

__global__ __launch_bounds__(512) void wo_convert(
    const float* __restrict__ Wo, __half* __restrict__ out)
{
    const int row = blockIdx.x, k = threadIdx.x;
    const float w = Wo[(size_t)row * INNER + k];
    __half hi, lo; split_f16(w, hi, lo);
    const size_t base = (size_t)row * K2P;
    out[base + k]       = hi;            // A-side: [hi | lo]
    out[base + 512 + k] = lo;
}

// ---------------- mma.sync fp16 GEMM ----------------
// D[m][n] = sum_k A[m][k]*B[n][k]; CTA tile 128x256, K-chunk 64, 3-stage cp.async.
// 8 warps as 2(M) x 4(N); warp tile 64x64 = 4x8 m16n8k16 fragments.
#define STG 49152   // per stage: A 128*128B (16KB) + B 256*128B (32KB)

__device__ __forceinline__ void stage_ld(uint32_t sA, uint32_t sB,
    const __half* __restrict__ Ag, int lda,
    const __half* __restrict__ Bg, int ldb, int kt, int tid)
{
    #pragma unroll
    for (int i = 0; i < 4; i++) {
        const int idx = tid + i * 256;
        const int row = idx >> 3, j = idx & 7;
        const uint32_t off = (uint32_t)(row * 128 + ((j ^ (row & 7)) * 16));
        cp_async16(sA + off, Ag + (size_t)row * lda + kt + j * 8);
    }
    #pragma unroll
    for (int i = 0; i < 8; i++) {
        const int idx = tid + i * 256;
        const int row = idx >> 3, j = idx & 7;
        const uint32_t off = (uint32_t)(row * 128 + ((j ^ (row & 7)) * 16));
        cp_async16(sB + off, Bg + (size_t)row * ldb + kt + j * 8);
    }
}

template <int T, int EPI>
__global__ __launch_bounds__(256) void hmma_gemm(
    const __half* __restrict__ A, int lda,
    const __half* __restrict__ B, int ldb,
    const float* __restrict__ bias, float* __restrict__ C, int ldc)
{
    extern __shared__ char dynraw[];
    const uint32_t smem = smem_u32(dynraw);
    const int tid = threadIdx.x;
    const int w = tid >> 5, l = tid & 31;
    const int wm = w >> 2, wn = w & 3;
    const int n0 = blockIdx.x * 256, m0 = blockIdx.y * 128;

    const __half* Ag = A + (size_t)m0 * lda;
    const __half* Bg = B + (size_t)n0 * ldb;

    float acc[4][8][4];
    #pragma unroll
    for (int i = 0; i < 4; i++)
        #pragma unroll
        for (int j = 0; j < 8; j++)
            #pragma unroll
            for (int c = 0; c < 4; c++) acc[i][j][c] = 0.f;

    // ldmatrix lane constants (all non-trans; K-major operands)
    const int arow_l = (l & 7) + ((l >> 3) & 1) * 8;   // A: row-in-16
    const int acol_l = (l >> 4) & 1;                   // A: k-half chunk
    const int brow_l = (l & 7) + ((l >> 4) & 1) * 8;   // B: n-row-in-16
    const int bcol_l = (l >> 3) & 1;                   // B: k-half chunk

    int abase[4], asw[4];
    #pragma unroll
    for (int i = 0; i < 4; i++) {
        const int mrow = wm * 64 + i * 16 + arow_l;
        abase[i] = mrow * 128;
        asw[i]   = mrow & 7;
    }
    int bbase[4], bsw[4];
    #pragma unroll
    for (int jj = 0; jj < 4; jj++) {
        const int nrow = wn * 64 + jj * 16 + brow_l;
        bbase[jj] = nrow * 128;
        bsw[jj]   = nrow & 7;
    }

    // Prologue: stages 0, 1
    stage_ld(smem,       smem + 16384,       Ag, lda, Bg, ldb, 0,  tid); cp_commit();
    stage_ld(smem + STG, smem + STG + 16384, Ag, lda, Bg, ldb, 64, tid); cp_commit();

    #pragma unroll 1
    for (int t = 0; t < T; t++) {
        cp_wait<1>();
        __syncthreads();
        if (t + 2 < T) {
            const int s2 = (t + 2) % 3;
            stage_ld(smem + s2 * STG, smem + s2 * STG + 16384,
                     Ag, lda, Bg, ldb, (t + 2) * 64, tid);
        }
        cp_commit();

        const uint32_t sA = smem + (t % 3) * STG;
        const uint32_t sB = sA + 16384;
        #pragma unroll
        for (int ks = 0; ks < 4; ks++) {
            uint32_t af[4][4];
            #pragma unroll
            for (int i = 0; i < 4; i++)
                ldsm_x4(sA + abase[i] + (((ks * 2 + acol_l) ^ asw[i]) * 16),
                        af[i][0], af[i][1], af[i][2], af[i][3]);
            uint32_t bf[8][2];
            #pragma unroll
            for (int jj = 0; jj < 4; jj++)
                ldsm_x4(sB + bbase[jj] + (((ks * 2 + bcol_l) ^ bsw[jj]) * 16),
                        bf[jj * 2][0], bf[jj * 2][1], bf[jj * 2 + 1][0], bf[jj * 2 + 1][1]);
            #pragma unroll
            for (int i = 0; i < 4; i++)
                #pragma unroll
                for (int j = 0; j < 8; j++)
                    mma16816(acc[i][j], af[i], bf[j]);
        }
    }

    // Epilogue: lane l holds rows (l>>2) and (l>>2)+8, cols 2*(l&3)
    const int r4 = l >> 2;
    const int c2 = (l & 3) * 2;
    #pragma unroll
    for (int i = 0; i < 4; i++) {
        const int row_a = m0 + wm * 64 + i * 16 + r4;
        #pragma unroll
        for (int h = 0; h < 2; h++) {
            const int row = row_a + h * 8;
            #pragma unroll
            for (int j = 0; j < 8; j++) {
                const int col = n0 + wn * 64 + j * 8 + c2;
                float2 v = make_float2(acc[i][j][h * 2], acc[i][j][h * 2 + 1]);
                if (EPI == 0) {
                    *(float2*)(C + (size_t)row * ldc + col) = v;
                } else {
                    const float bv = bias[row];
                    const int bb = col / HW;
                    const int hw = col - bb * HW;
                    v.x += bv; v.y += bv;
                    *(float2*)(C + ((size_t)bb * DIMC + row) * HW + hw) = v;
                }
            }
        }
    }
}

// ---------------- attention: warp per (pixel, head), no smem ----------------
__global__ __launch_bounds__(256) void attn_kernel(
    const float* __restrict__ qkvT, __half* __restrict__ aoT)
{
    const int l  = threadIdx.x & 31;
    const int x  = blockIdx.x * 8 + (threadIdx.x >> 5);
    const int y  = blockIdx.y;
    const int head = blockIdx.z & (HEADS - 1);
    const int b    = blockIdx.z >> 3;

    const size_t pbase = (size_t)(b * HW + y * IMG_W + x) * QKV_CH;
    const int chb = head * DHEAD + l * 2;

    const float2 q = *(const float2*)(qkvT + pbase + chb);

    float dots[9];
    #pragma unroll
    for (int t = 0; t < 9; t++) {
        const int yy = y + t / 3 - 1;
        const int xx = x + t % 3 - 1;
        float d = 0.f;
        if (yy >= 0 && yy < IMG_H && xx >= 0 && xx < IMG_W) {
            const float2 kk = *(const float2*)(
                qkvT + (size_t)(b * HW + yy * IMG_W + xx) * QKV_CH + INNER + chb);
            d = fmaf(q.x, kk.x, q.y * kk.y);
        }
        dots[t] = d;
    }
    #pragma unroll
    for (int off = 16; off; off >>= 1)
        #pragma unroll
        for (int t = 0; t < 9; t++)
            dots[t] += __shfl_xor_sync(0xFFFFFFFFu, dots[t], off);

    float m = -1e30f;
    #pragma unroll
    for (int t = 0; t < 9; t++) { dots[t] *= SCALE; m = fmaxf(m, dots[t]); }
    float wgt[9], s = 0.f;
    #pragma unroll
    for (int t = 0; t < 9; t++) { wgt[t] = __expf(dots[t] - m); s += wgt[t]; }
    const float inv = 1.f / s;

    float2 o = make_float2(0.f, 0.f);
    #pragma unroll
    for (int t = 0; t < 9; t++) {
        const int yy = y + t / 3 - 1;
        const int xx = x + t % 3 - 1;
        if (yy >= 0 && yy < IMG_H && xx >= 0 && xx < IMG_W) {
            const float2 vv = *(const float2*)(
                qkvT + (size_t)(b * HW + yy * IMG_W + xx) * QKV_CH + 2 * INNER + chb);
            const float wt = wgt[t] * inv;
            o.x = fmaf(wt, vv.x, o.x);
            o.y = fmaf(wt, vv.y, o.y);
        }
    }

    // B-side [hi | hi]: GEMM2's A-side (wo) carries the lo split.
    __half2 hi2;
    hi2.x = __float2half(o.x);
    hi2.y = __float2half(o.y);
    __half* dst = aoT + (size_t)(b * HW + y * IMG_W + x) * K2P + chb;
    *(__half2*)(dst)       = hi2;
    *(__half2*)(dst + 512) = hi2;
}

// ---------------- launch ----------------
extern "C" void kernel_launch(void* const* d_in, const int* in_sizes, int n_in,
                              void* d_out, int out_size)
{
    const float* x   = (const float*)d_in[0];
    const float* Wq  = (const float*)d_in[1];
    const float* Wkv = (const float*)d_in[2];
    const float* Wo  = (const float*)d_in[3];
    const float* bo  = (const float*)d_in[4];
    float* out = (float*)d_out;

    __half *xT, *wqkv, *wo, *aoT;
    float* qkvT;
    cudaGetSymbolAddress((void**)&xT,   g_xT);
    cudaGetSymbolAddress((void**)&wqkv, g_wqkv);
    cudaGetSymbolAddress((void**)&wo,   g_wo);
    cudaGetSymbolAddress((void**)&qkvT, g_qkvT);
    cudaGetSymbolAddress((void**)&aoT,  g_aoT);

    const int gemm_smem = 3 * STG;   // 144 KB
    cudaFuncSetAttribute(hmma_gemm<K1P / 64, 0>,
                         cudaFuncAttributeMaxDynamicSharedMemorySize, gemm_smem);
    cudaFuncSetAttribute(hmma_gemm<K2P / 64, 1>,
                         cudaFuncAttributeMaxDynamicSharedMemorySize, gemm_smem);

    // 0) converts
    transpose_convert<<<dim3(HW / 32, DIMC / 32, BATCH), dim3(32, 8)>>>(x, xT);
    wqkv_convert<<<QKV_CH, DIMC>>>(Wq, Wkv, wqkv);
    wo_convert<<<DIMC, INNER>>>(Wo, wo);

    // 1) qkv projection: D[p][ch], M=12544, N=1536, K'=768
    hmma_gemm<K1P / 64, 0><<<dim3(QKV_CH / 256, NPIX / 128), 256, gemm_smem>>>(
        xT, K1P, wqkv, K1P, nullptr, qkvT, QKV_CH);

    // 2) neighborhood attention (warp per pixel-head)
    attn_kernel<<<dim3(IMG_W / 8, IMG_H, BATCH * HEADS), 256>>>(qkvT, aoT);

    // 3) out projection: D[ch][p] -> out (channel-major) + bias, M=384, N=12544, K'=1024
    hmma_gemm<K2P / 64, 1><<<dim3(NPIX / 256, DIMC / 128), 256, gemm_smem>>>(
        wo, K2P, aoT, K2P, bo, out, 0);
}

// round 8
// speedup vs baseline: 3.2668x; 1.0106x over previous
#include <cuda_runtime.h>
#include <cuda_fp16.h>
#include <cstdint>
#include <cstddef>

#define BATCH   4
#define DIMC    384
#define HEADS   8
#define DHEAD   64
#define INNER   512
#define QKV_CH  1536
#define IMG_H   56
#define IMG_W   56
#define HW      3136
#define NPIX    (BATCH * HW)      // 12544
#define SCALE   0.125f

#define K1P     768               // A-side K' = 2*384 ([hi|lo]); B stored once (384)
#define K2P     1024              // A-side K' = 2*512 ([hi|lo]); B stored once (512)

// Scratch (device globals; allocation forbidden)
__device__ __half g_xT  [(size_t)NPIX * K1P];     // A1: [hi|lo] of x, pixel-major
__device__ __half g_wqkv[(size_t)QKV_CH * DIMC];  // B1: hi only (k-dedup)
__device__ __half g_wo  [(size_t)DIMC * K2P];     // A2: [hi|lo] of Wo
__device__ float  g_qkvT[(size_t)NPIX * QKV_CH];  // pixel-major q|k|v
__device__ __half g_aoT [(size_t)NPIX * INNER];   // B2: hi only (k-dedup)

// ---------------- PTX helpers (baseline sm_80+ features only) ----------------
__device__ __forceinline__ uint32_t smem_u32(const void* p) {
    uint32_t a;
    asm("{ .reg .u64 t; cvta.to.shared.u64 t, %1; cvt.u32.u64 %0, t; }" : "=r"(a) : "l"(p));
    return a;
}
__device__ __forceinline__ void cp_async16(uint32_t saddr, const void* gptr) {
    asm volatile("cp.async.cg.shared.global [%0], [%1], 16;\n" :: "r"(saddr), "l"(gptr));
}
__device__ __forceinline__ void cp_commit() {
    asm volatile("cp.async.commit_group;\n" ::: "memory");
}
template <int N> __device__ __forceinline__ void cp_wait() {
    asm volatile("cp.async.wait_group %0;\n" :: "n"(N) : "memory");
}
__device__ __forceinline__ void ldsm_x4(uint32_t addr, uint32_t& r0, uint32_t& r1,
                                        uint32_t& r2, uint32_t& r3) {
    asm volatile("ldmatrix.sync.aligned.m8n8.x4.shared.b16 {%0,%1,%2,%3}, [%4];"
                 : "=r"(r0), "=r"(r1), "=r"(r2), "=r"(r3) : "r"(addr));
}
__device__ __forceinline__ void mma16816(float* d, const uint32_t* a, const uint32_t* b) {
    asm volatile("mma.sync.aligned.m16n8k16.row.col.f32.f16.f16.f32 "
        "{%0,%1,%2,%3}, {%4,%5,%6,%7}, {%8,%9}, {%0,%1,%2,%3};"
        : "+f"(d[0]), "+f"(d[1]), "+f"(d[2]), "+f"(d[3])
        : "r"(a[0]), "r"(a[1]), "r"(a[2]), "r"(a[3]), "r"(b[0]), "r"(b[1]));
}

// ---------------- input converts ----------------
__device__ __forceinline__ void split_f16(float v, __half& hi, __half& lo) {
    hi = __float2half(v);
    lo = __float2half(v - __half2float(hi));
}

__global__ __launch_bounds__(256) void transpose_convert(
    const float* __restrict__ x, __half* __restrict__ xT)
{
    __shared__ float t[32][33];
    const int p0 = blockIdx.x * 32, c0 = blockIdx.y * 32, b = blockIdx.z;
    const int tx = threadIdx.x, ty = threadIdx.y;
    const float* src = x + (size_t)b * DIMC * HW;
    #pragma unroll
    for (int i = 0; i < 32; i += 8)
        t[ty + i][tx] = src[(size_t)(c0 + ty + i) * HW + p0 + tx];
    __syncthreads();
    __half* dst = xT + (size_t)b * HW * K1P;
    #pragma unroll
    for (int i = 0; i < 32; i += 8) {
        const float v = t[tx][ty + i];
        __half hi, lo; split_f16(v, hi, lo);
        const size_t row = (size_t)(p0 + ty + i) * K1P;
        dst[row + c0 + tx]       = hi;   // A-side: [hi | lo]
        dst[row + 384 + c0 + tx] = lo;
    }
}

// Merged weight converts: blocks [0,1536) -> wqkv hi; [1536,1920) -> wo [hi|lo]
__global__ __launch_bounds__(512) void weights_convert(
    const float* __restrict__ Wq, const float* __restrict__ Wkv,
    const float* __restrict__ Wo,
    __half* __restrict__ wqkv, __half* __restrict__ wo)
{
    const int blk = blockIdx.x;
    const int k = threadIdx.x;
    if (blk < QKV_CH) {
        if (k < DIMC) {
            const float w = (blk < INNER) ? Wq[(size_t)blk * DIMC + k]
                                          : Wkv[(size_t)(blk - INNER) * DIMC + k];
            wqkv[(size_t)blk * DIMC + k] = __float2half(w);   // B1: hi only
        }
    } else {
        const int row = blk - QKV_CH;
        const float w = Wo[(size_t)row * INNER + k];
        __half hi, lo; split_f16(w, hi, lo);
        const size_t base = (size_t)row * K2P;
        wo[base + k]       = hi;                               // A2: [hi | lo]
        wo[base + 512 + k] = lo;
    }
}

// ---------------- mma.sync fp16 GEMM ----------------
// D[m][n] = sum_{k'} A[m][k'] * B[n][k' % KB]   (A K'=2*KB [hi|lo], B stored once)
// CTA tile 128x256, K-chunk 64, 3-stage cp.async. 8 warps 2(M)x4(N), warp 64x64.
#define STG 49152   // per stage: A 128*128B (16KB) + B 256*128B (32KB)

__device__ __forceinline__ void stage_ld(uint32_t sA, uint32_t sB,
    const __half* __restrict__ Ag, int lda, int kta,
    const __half* __restrict__ Bg, int ldb, int ktb, int tid)
{
    #pragma unroll
    for (int i = 0; i < 4; i++) {
        const int idx = tid + i * 256;
        const int row = idx >> 3, j = idx & 7;
        const uint32_t off = (uint32_t)(row * 128 + ((j ^ (row & 7)) * 16));
        cp_async16(sA + off, Ag + (size_t)row * lda + kta + j * 8);
    }
    #pragma unroll
    for (int i = 0; i < 8; i++) {
        const int idx = tid + i * 256;
        const int row = idx >> 3, j = idx & 7;
        const uint32_t off = (uint32_t)(row * 128 + ((j ^ (row & 7)) * 16));
        cp_async16(sB + off, Bg + (size_t)row * ldb + ktb + j * 8);
    }
}

template <int T, int KB, int EPI>
__global__ __launch_bounds__(256) void hmma_gemm(
    const __half* __restrict__ A, int lda,
    const __half* __restrict__ B, int ldb,
    const float* __restrict__ bias, float* __restrict__ C, int ldc)
{
    extern __shared__ char dynraw[];
    const uint32_t smem = smem_u32(dynraw);
    const int tid = threadIdx.x;
    const int w = tid >> 5, l = tid & 31;
    const int wm = w >> 2, wn = w & 3;
    const int n0 = blockIdx.x * 256, m0 = blockIdx.y * 128;

    const __half* Ag = A + (size_t)m0 * lda;
    const __half* Bg = B + (size_t)n0 * ldb;

    float acc[4][8][4];
    #pragma unroll
    for (int i = 0; i < 4; i++)
        #pragma unroll
        for (int j = 0; j < 8; j++)
            #pragma unroll
            for (int c = 0; c < 4; c++) acc[i][j][c] = 0.f;

    // ldmatrix lane constants (all non-trans; K-major operands)
    const int arow_l = (l & 7) + ((l >> 3) & 1) * 8;   // A: row-in-16
    const int acol_l = (l >> 4) & 1;                   // A: k-half chunk
    const int brow_l = (l & 7) + ((l >> 4) & 1) * 8;   // B: n-row-in-16
    const int bcol_l = (l >> 3) & 1;                   // B: k-half chunk

    int abase[4], asw[4];
    #pragma unroll
    for (int i = 0; i < 4; i++) {
        const int mrow = wm * 64 + i * 16 + arow_l;
        abase[i] = mrow * 128;
        asw[i]   = mrow & 7;
    }
    int bbase[4], bsw[4];
    #pragma unroll
    for (int jj = 0; jj < 4; jj++) {
        const int nrow = wn * 64 + jj * 16 + brow_l;
        bbase[jj] = nrow * 128;
        bsw[jj]   = nrow & 7;
    }

    // ks-stagger: warps sharing an SMSP (w and w+4) start at different ks
    const int ks0 = ((w >> 2) & 1) << 1;

    // Prologue: stages 0, 1 (kt=0,64 both < KB)
    stage_ld(smem,       smem + 16384,       Ag, lda, 0,  Bg, ldb, 0,  tid); cp_commit();
    stage_ld(smem + STG, smem + STG + 16384, Ag, lda, 64, Bg, ldb, 64, tid); cp_commit();

    #pragma unroll 1
    for (int t = 0; t < T; t++) {
        cp_wait<1>();
        __syncthreads();
        if (t + 2 < T) {
            const int s2 = (t + 2) % 3;
            const int kt2 = (t + 2) * 64;
            const int ktb2 = (kt2 >= KB) ? kt2 - KB : kt2;
            stage_ld(smem + s2 * STG, smem + s2 * STG + 16384,
                     Ag, lda, kt2, Bg, ldb, ktb2, tid);
        }
        cp_commit();

        const uint32_t sA = smem + (t % 3) * STG;
        const uint32_t sB = sA + 16384;
        #pragma unroll
        for (int kss = 0; kss < 4; kss++) {
            const int ks = (kss + ks0) & 3;
            uint32_t af[4][4];
            #pragma unroll
            for (int i = 0; i < 4; i++)
                ldsm_x4(sA + abase[i] + (((ks * 2 + acol_l) ^ asw[i]) * 16),
                        af[i][0], af[i][1], af[i][2], af[i][3]);
            uint32_t bf[8][2];
            #pragma unroll
            for (int jj = 0; jj < 4; jj++)
                ldsm_x4(sB + bbase[jj] + (((ks * 2 + bcol_l) ^ bsw[jj]) * 16),
                        bf[jj * 2][0], bf[jj * 2][1], bf[jj * 2 + 1][0], bf[jj * 2 + 1][1]);
            #pragma unroll
            for (int i = 0; i < 4; i++)
                #pragma unroll
                for (int j = 0; j < 8; j++)
                    mma16816(acc[i][j], af[i], bf[j]);
        }
    }

    // Epilogue: lane l holds rows (l>>2) and (l>>2)+8, cols 2*(l&3)
    const int r4 = l >> 2;
    const int c2 = (l & 3) * 2;
    #pragma unroll
    for (int i = 0; i < 4; i++) {
        const int row_a = m0 + wm * 64 + i * 16 + r4;
        #pragma unroll
        for (int h = 0; h < 2; h++) {
            const int row = row_a + h * 8;
            #pragma unroll
            for (int j = 0; j < 8; j++) {
                const int col = n0 + wn * 64 + j * 8 + c2;
                float2 v = make_float2(acc[i][j][h * 2], acc[i][j][h * 2 + 1]);
                if (EPI == 0) {
                    *(float2*)(C + (size_t)row * ldc + col) = v;
                } else {
                    const float bv = bias[row];
                    const int bb = col / HW;
                    const int hw = col - bb * HW;
                    v.x += bv; v.y += bv;
                    *(float2*)(C + ((size_t)bb * DIMC + row) * HW + hw) = v;
                }
            }
        }
    }
}

// ---------------- attention: warp per (pixel, head), no smem ----------------
__global__ __launch_bounds__(256) void attn_kernel(
    const float* __restrict__ qkvT, __half* __restrict__ aoT)
{
    const int l  = threadIdx.x & 31;
    const int x  = blockIdx.x * 8 + (threadIdx.x >> 5);
    const int y  = blockIdx.y;
    const int head = blockIdx.z & (HEADS - 1);
    const int b    = blockIdx.z >> 3;

    const size_t pbase = (size_t)(b * HW + y * IMG_W + x) * QKV_CH;
    const int chb = head * DHEAD + l * 2;

    const float2 q = *(const float2*)(qkvT + pbase + chb);

    float dots[9];
    #pragma unroll
    for (int t = 0; t < 9; t++) {
        const int yy = y + t / 3 - 1;
        const int xx = x + t % 3 - 1;
        float d = 0.f;
        if (yy >= 0 && yy < IMG_H && xx >= 0 && xx < IMG_W) {
            const float2 kk = *(const float2*)(
                qkvT + (size_t)(b * HW + yy * IMG_W + xx) * QKV_CH + INNER + chb);
            d = fmaf(q.x, kk.x, q.y * kk.y);
        }
        dots[t] = d;
    }
    #pragma unroll
    for (int off = 16; off; off >>= 1)
        #pragma unroll
        for (int t = 0; t < 9; t++)
            dots[t] += __shfl_xor_sync(0xFFFFFFFFu, dots[t], off);

    float m = -1e30f;
    #pragma unroll
    for (int t = 0; t < 9; t++) { dots[t] *= SCALE; m = fmaxf(m, dots[t]); }
    float wgt[9], s = 0.f;
    #pragma unroll
    for (int t = 0; t < 9; t++) { wgt[t] = __expf(dots[t] - m); s += wgt[t]; }
    const float inv = 1.f / s;

    float2 o = make_float2(0.f, 0.f);
    #pragma unroll
    for (int t = 0; t < 9; t++) {
        const int yy = y + t / 3 - 1;
        const int xx = x + t % 3 - 1;
        if (yy >= 0 && yy < IMG_H && xx >= 0 && xx < IMG_W) {
            const float2 vv = *(const float2*)(
                qkvT + (size_t)(b * HW + yy * IMG_W + xx) * QKV_CH + 2 * INNER + chb);
            const float wt = wgt[t] * inv;
            o.x = fmaf(wt, vv.x, o.x);
            o.y = fmaf(wt, vv.y, o.y);
        }
    }

    // B2 stored once (hi); GEMM2's A (wo) carries the lo split.
    __half2 hi2;
    hi2.x = __float2half(o.x);
    hi2.y = __float2half(o.y);
    *(__half2*)(aoT + (size_t)(b * HW + y * IMG_W + x) * INNER + chb) = hi2;
}

// ---------------- launch ----------------
extern "C" void kernel_launch(void* const* d_in, const int* in_sizes, int n_in,
                              void* d_out, int out_size)
{
    const float* x   = (const float*)d_in[0];
    const float* Wq  = (const float*)d_in[1];
    const float* Wkv = (const float*)d_in[2];
    const float* Wo  = (const float*)d_in[3];
    const float* bo  = (const float*)d_in[4];
    float* out = (float*)d_out;

    __half *xT, *wqkv, *wo, *aoT;
    float* qkvT;
    cudaGetSymbolAddress((void**)&xT,   g_xT);
    cudaGetSymbolAddress((void**)&wqkv, g_wqkv);
    cudaGetSymbolAddress((void**)&wo,   g_wo);
    cudaGetSymbolAddress((void**)&qkvT, g_qkvT);
    cudaGetSymbolAddress((void**)&aoT,  g_aoT);

    const int gemm_smem = 3 * STG;   // 144 KB
    cudaFuncSetAttribute((const void*)hmma_gemm<K1P / 64, DIMC, 0>,
                         cudaFuncAttributeMaxDynamicSharedMemorySize, gemm_smem);
    cudaFuncSetAttribute((const void*)hmma_gemm<K2P / 64, INNER, 1>,
                         cudaFuncAttributeMaxDynamicSharedMemorySize, gemm_smem);

    // 0) converts
    weights_convert<<<QKV_CH + DIMC, 512>>>(Wq, Wkv, Wo, wqkv, wo);
    transpose_convert<<<dim3(HW / 32, DIMC / 32, BATCH), dim3(32, 8)>>>(x, xT);

    // 1) qkv projection: D[p][ch], M=12544, N=1536, K'=768 (B dedup 384)
    hmma_gemm<K1P / 64, DIMC, 0><<<dim3(QKV_CH / 256, NPIX / 128), 256, gemm_smem>>>(
        xT, K1P, wqkv, DIMC, nullptr, qkvT, QKV_CH);

    // 2) neighborhood attention (warp per pixel-head)
    attn_kernel<<<dim3(IMG_W / 8, IMG_H, BATCH * HEADS), 256>>>(qkvT, aoT);

    // 3) out projection: D[ch][p] -> out (channel-major) + bias, K'=1024 (B dedup 512)
    hmma_gemm<K2P / 64, INNER, 1><<<dim3(NPIX / 256, DIMC / 128), 256, gemm_smem>>>(
        wo, K2P, aoT, INNER, bo, out, 0);
}

// round 9
// speedup vs baseline: 3.5346x; 1.0820x over previous
#include <cuda_runtime.h>
#include <cuda_fp16.h>
#include <cstdint>
#include <cstddef>

#define BATCH   4
#define DIMC    384
#define HEADS   8
#define DHEAD   64
#define INNER   512
#define QKV_CH  1536
#define IMG_H   56
#define IMG_W   56
#define HW      3136
#define NPIX    (BATCH * HW)      // 12544
#define SCALE   0.125f

#define K1P     768               // A-side K' = 2*384 ([hi|lo]); B stored once (384)
#define K2P     1024              // A-side K' = 2*512 ([hi|lo]); B stored once (512)

// Scratch (device globals; allocation forbidden)
__device__ __half g_xT  [(size_t)NPIX * K1P];     // A1: [hi|lo] of x, pixel-major
__device__ __half g_wqkv[(size_t)QKV_CH * DIMC];  // B1: hi only (k-dedup)
__device__ __half g_wo  [(size_t)DIMC * K2P];     // A2: [hi|lo] of Wo
__device__ float  g_qkvT[(size_t)NPIX * QKV_CH];  // pixel-major q|k|v
__device__ __half g_aoT [(size_t)NPIX * INNER];   // B2: hi only (k-dedup)

// ---------------- PTX helpers (baseline sm_80+ features only) ----------------
__device__ __forceinline__ uint32_t smem_u32(const void* p) {
    uint32_t a;
    asm("{ .reg .u64 t; cvta.to.shared.u64 t, %1; cvt.u32.u64 %0, t; }" : "=r"(a) : "l"(p));
    return a;
}
__device__ __forceinline__ void cp_async16(uint32_t saddr, const void* gptr) {
    asm volatile("cp.async.cg.shared.global [%0], [%1], 16;\n" :: "r"(saddr), "l"(gptr));
}
__device__ __forceinline__ void cp_commit() {
    asm volatile("cp.async.commit_group;\n" ::: "memory");
}
template <int N> __device__ __forceinline__ void cp_wait() {
    asm volatile("cp.async.wait_group %0;\n" :: "n"(N) : "memory");
}
__device__ __forceinline__ void ldsm_x4(uint32_t addr, uint32_t& r0, uint32_t& r1,
                                        uint32_t& r2, uint32_t& r3) {
    asm volatile("ldmatrix.sync.aligned.m8n8.x4.shared.b16 {%0,%1,%2,%3}, [%4];"
                 : "=r"(r0), "=r"(r1), "=r"(r2), "=r"(r3) : "r"(addr));
}
__device__ __forceinline__ void mma16816(float* d, const uint32_t* a, const uint32_t* b) {
    asm volatile("mma.sync.aligned.m16n8k16.row.col.f32.f16.f16.f32 "
        "{%0,%1,%2,%3}, {%4,%5,%6,%7}, {%8,%9}, {%0,%1,%2,%3};"
        : "+f"(d[0]), "+f"(d[1]), "+f"(d[2]), "+f"(d[3])
        : "r"(a[0]), "r"(a[1]), "r"(a[2]), "r"(a[3]), "r"(b[0]), "r"(b[1]));
}

// ---------------- input converts ----------------
__device__ __forceinline__ void split_f16(float v, __half& hi, __half& lo) {
    hi = __float2half(v);
    lo = __float2half(v - __half2float(hi));
}

__global__ __launch_bounds__(256) void transpose_convert(
    const float* __restrict__ x, __half* __restrict__ xT)
{
    __shared__ float t[32][33];
    const int p0 = blockIdx.x * 32, c0 = blockIdx.y * 32, b = blockIdx.z;
    const int tx = threadIdx.x, ty = threadIdx.y;
    const float* src = x + (size_t)b * DIMC * HW;
    #pragma unroll
    for (int i = 0; i < 32; i += 8)
        t[ty + i][tx] = src[(size_t)(c0 + ty + i) * HW + p0 + tx];
    __syncthreads();
    __half* dst = xT + (size_t)b * HW * K1P;
    #pragma unroll
    for (int i = 0; i < 32; i += 8) {
        const float v = t[tx][ty + i];
        __half hi, lo; split_f16(v, hi, lo);
        const size_t row = (size_t)(p0 + ty + i) * K1P;
        dst[row + c0 + tx]       = hi;   // A-side: [hi | lo]
        dst[row + 384 + c0 + tx] = lo;
    }
}

// Merged weight converts: blocks [0,1536) -> wqkv hi; [1536,1920) -> wo [hi|lo]
__global__ __launch_bounds__(512) void weights_convert(
    const float* __restrict__ Wq, const float* __restrict__ Wkv,
    const float* __restrict__ Wo,
    __half* __restrict__ wqkv, __half* __restrict__ wo)
{
    const int blk = blockIdx.x;
    const int k = threadIdx.x;
    if (blk < QKV_CH) {
        if (k < DIMC) {
            const float w = (blk < INNER) ? Wq[(size_t)blk * DIMC + k]
                                          : Wkv[(size_t)(blk - INNER) * DIMC + k];
            wqkv[(size_t)blk * DIMC + k] = __float2half(w);   // B1: hi only
        }
    } else {
        const int row = blk - QKV_CH;
        const float w = Wo[(size_t)row * INNER + k];
        __half hi, lo; split_f16(w, hi, lo);
        const size_t base = (size_t)row * K2P;
        wo[base + k]       = hi;                               // A2: [hi | lo]
        wo[base + 512 + k] = lo;
    }
}

// ---------------- mma.sync fp16 GEMM ----------------
// D[m][n] = sum_{k'} A[m][k'] * B[n][k' % KB]   (A K'=2*KB [hi|lo], B stored once)
// CTA tile 128x256, K-chunk 64, 3-stage cp.async. 8 warps 2(M)x4(N), warp 64x64.
#define STG 49152   // per stage: A 128*128B (16KB) + B 256*128B (32KB)

__device__ __forceinline__ void stage_ld(uint32_t sA, uint32_t sB,
    const __half* __restrict__ Ag, int lda, int kta,
    const __half* __restrict__ Bg, int ldb, int ktb, int tid)
{
    #pragma unroll
    for (int i = 0; i < 4; i++) {
        const int idx = tid + i * 256;
        const int row = idx >> 3, j = idx & 7;
        const uint32_t off = (uint32_t)(row * 128 + ((j ^ (row & 7)) * 16));
        cp_async16(sA + off, Ag + (size_t)row * lda + kta + j * 8);
    }
    #pragma unroll
    for (int i = 0; i < 8; i++) {
        const int idx = tid + i * 256;
        const int row = idx >> 3, j = idx & 7;
        const uint32_t off = (uint32_t)(row * 128 + ((j ^ (row & 7)) * 16));
        cp_async16(sB + off, Bg + (size_t)row * ldb + ktb + j * 8);
    }
}

template <int T, int KB, int EPI>
__global__ __launch_bounds__(256) void hmma_gemm(
    const __half* __restrict__ A, int lda,
    const __half* __restrict__ B, int ldb,
    const float* __restrict__ bias, float* __restrict__ C, int ldc)
{
    extern __shared__ char dynraw[];
    const uint32_t smem = smem_u32(dynraw);
    const int tid = threadIdx.x;
    const int w = tid >> 5, l = tid & 31;
    const int wm = w >> 2, wn = w & 3;
    const int n0 = blockIdx.x * 256, m0 = blockIdx.y * 128;

    const __half* Ag = A + (size_t)m0 * lda;
    const __half* Bg = B + (size_t)n0 * ldb;

    float acc[4][8][4];
    #pragma unroll
    for (int i = 0; i < 4; i++)
        #pragma unroll
        for (int j = 0; j < 8; j++)
            #pragma unroll
            for (int c = 0; c < 4; c++) acc[i][j][c] = 0.f;

    // ldmatrix lane constants (all non-trans; K-major operands)
    const int arow_l = (l & 7) + ((l >> 3) & 1) * 8;   // A: row-in-16
    const int acol_l = (l >> 4) & 1;                   // A: k-half chunk
    const int brow_l = (l & 7) + ((l >> 4) & 1) * 8;   // B: n-row-in-16
    const int bcol_l = (l >> 3) & 1;                   // B: k-half chunk

    int abase[4], asw[4];
    #pragma unroll
    for (int i = 0; i < 4; i++) {
        const int mrow = wm * 64 + i * 16 + arow_l;
        abase[i] = mrow * 128;
        asw[i]   = mrow & 7;
    }
    int bbase[4], bsw[4];
    #pragma unroll
    for (int jj = 0; jj < 4; jj++) {
        const int nrow = wn * 64 + jj * 16 + brow_l;
        bbase[jj] = nrow * 128;
        bsw[jj]   = nrow & 7;
    }

    // ks-stagger: warps sharing an SMSP (w and w+4) start at different ks
    const int ks0 = ((w >> 2) & 1) << 1;

    // Prologue: stages 0, 1 (kt=0,64 both < KB)
    stage_ld(smem,       smem + 16384,       Ag, lda, 0,  Bg, ldb, 0,  tid); cp_commit();
    stage_ld(smem + STG, smem + STG + 16384, Ag, lda, 64, Bg, ldb, 64, tid); cp_commit();

    #pragma unroll 1
    for (int t = 0; t < T; t++) {
        cp_wait<1>();
        __syncthreads();
        if (t + 2 < T) {
            const int s2 = (t + 2) % 3;
            const int kt2 = (t + 2) * 64;
            const int ktb2 = (kt2 >= KB) ? kt2 - KB : kt2;
            stage_ld(smem + s2 * STG, smem + s2 * STG + 16384,
                     Ag, lda, kt2, Bg, ldb, ktb2, tid);
        }
        cp_commit();

        const uint32_t sA = smem + (t % 3) * STG;
        const uint32_t sB = sA + 16384;
        #pragma unroll
        for (int kss = 0; kss < 4; kss++) {
            const int ks = (kss + ks0) & 3;
            uint32_t af[4][4];
            #pragma unroll
            for (int i = 0; i < 4; i++)
                ldsm_x4(sA + abase[i] + (((ks * 2 + acol_l) ^ asw[i]) * 16),
                        af[i][0], af[i][1], af[i][2], af[i][3]);
            uint32_t bf[8][2];
            #pragma unroll
            for (int jj = 0; jj < 4; jj++)
                ldsm_x4(sB + bbase[jj] + (((ks * 2 + bcol_l) ^ bsw[jj]) * 16),
                        bf[jj * 2][0], bf[jj * 2][1], bf[jj * 2 + 1][0], bf[jj * 2 + 1][1]);
            #pragma unroll
            for (int i = 0; i < 4; i++)
                #pragma unroll
                for (int j = 0; j < 8; j++)
                    mma16816(acc[i][j], af[i], bf[j]);
        }
    }

    // Epilogue: lane l holds rows (l>>2) and (l>>2)+8, cols 2*(l&3)
    const int r4 = l >> 2;
    const int c2 = (l & 3) * 2;
    #pragma unroll
    for (int i = 0; i < 4; i++) {
        const int row_a = m0 + wm * 64 + i * 16 + r4;
        #pragma unroll
        for (int h = 0; h < 2; h++) {
            const int row = row_a + h * 8;
            #pragma unroll
            for (int j = 0; j < 8; j++) {
                const int col = n0 + wn * 64 + j * 8 + c2;
                float2 v = make_float2(acc[i][j][h * 2], acc[i][j][h * 2 + 1]);
                if (EPI == 0) {
                    *(float2*)(C + (size_t)row * ldc + col) = v;
                } else {
                    const float bv = bias[row];
                    const int bb = col / HW;
                    const int hw = col - bb * HW;
                    v.x += bv; v.y += bv;
                    *(float2*)(C + ((size_t)bb * DIMC + row) * HW + hw) = v;
                }
            }
        }
    }
}

// ---------------- attention: warp per (pixel, head-pair) ----------------
// Lane owns 4 consecutive d of ONE head: lanes 0-15 -> head 2*hp, 16-31 -> 2*hp+1.
// Dot reduction = 4-stage butterfly within 16-lane groups. Interior fast path
// (93% of pixels, warp-uniform) skips all bounds checks.
__global__ __launch_bounds__(256) void attn_kernel(
    const float* __restrict__ qkvT, __half* __restrict__ aoT)
{
    const int w  = threadIdx.x >> 5;
    const int l  = threadIdx.x & 31;
    const int x  = blockIdx.x * 2 + (w >> 2);
    const int y  = blockIdx.y;
    const int b  = blockIdx.z;
    const int hp = w & 3;                  // head pair 0..3
    const int chb = hp * 128 + l * 4;      // offset within 512-channel block

    const float* base = qkvT + (size_t)(b * HW + y * IMG_W + x) * QKV_CH;
    const float4 q = *(const float4*)(base + chb);

    const bool interior = (x >= 1) && (x <= IMG_W - 2) && (y >= 1) && (y <= IMG_H - 2);

    float dots[9];
    if (interior) {
        #pragma unroll
        for (int r = 0; r < 3; r++) {
            const float* krow = base + ((r - 1) * IMG_W - 1) * QKV_CH + INNER + chb;
            #pragma unroll
            for (int c = 0; c < 3; c++) {
                const float4 kk = *(const float4*)(krow + c * QKV_CH);
                dots[r * 3 + c] = fmaf(q.x, kk.x,
                                  fmaf(q.y, kk.y,
                                  fmaf(q.z, kk.z, q.w * kk.w)));
            }
        }
    } else {
        #pragma unroll
        for (int t = 0; t < 9; t++) {
            const int yy = y + t / 3 - 1;
            const int xx = x + t % 3 - 1;
            float d = 0.f;
            if (yy >= 0 && yy < IMG_H && xx >= 0 && xx < IMG_W) {
                const float4 kk = *(const float4*)(
                    qkvT + (size_t)(b * HW + yy * IMG_W + xx) * QKV_CH + INNER + chb);
                d = fmaf(q.x, kk.x, fmaf(q.y, kk.y, fmaf(q.z, kk.z, q.w * kk.w)));
            }
            dots[t] = d;
        }
    }

    // 4-stage butterfly within each 16-lane (one-head) group
    #pragma unroll
    for (int off = 8; off; off >>= 1)
        #pragma unroll
        for (int t = 0; t < 9; t++)
            dots[t] += __shfl_xor_sync(0xFFFFFFFFu, dots[t], off);

    float m = -1e30f;
    #pragma unroll
    for (int t = 0; t < 9; t++) { dots[t] *= SCALE; m = fmaxf(m, dots[t]); }
    float wgt[9], s = 0.f;
    #pragma unroll
    for (int t = 0; t < 9; t++) { wgt[t] = __expf(dots[t] - m); s += wgt[t]; }
    const float inv = 1.f / s;
    #pragma unroll
    for (int t = 0; t < 9; t++) wgt[t] *= inv;

    float4 o = make_float4(0.f, 0.f, 0.f, 0.f);
    if (interior) {
        #pragma unroll
        for (int r = 0; r < 3; r++) {
            const float* vrow = base + ((r - 1) * IMG_W - 1) * QKV_CH + 2 * INNER + chb;
            #pragma unroll
            for (int c = 0; c < 3; c++) {
                const float4 vv = *(const float4*)(vrow + c * QKV_CH);
                const float wt = wgt[r * 3 + c];
                o.x = fmaf(wt, vv.x, o.x);
                o.y = fmaf(wt, vv.y, o.y);
                o.z = fmaf(wt, vv.z, o.z);
                o.w = fmaf(wt, vv.w, o.w);
            }
        }
    } else {
        #pragma unroll
        for (int t = 0; t < 9; t++) {
            const int yy = y + t / 3 - 1;
            const int xx = x + t % 3 - 1;
            if (yy >= 0 && yy < IMG_H && xx >= 0 && xx < IMG_W) {
                const float4 vv = *(const float4*)(
                    qkvT + (size_t)(b * HW + yy * IMG_W + xx) * QKV_CH + 2 * INNER + chb);
                const float wt = wgt[t];
                o.x = fmaf(wt, vv.x, o.x);
                o.y = fmaf(wt, vv.y, o.y);
                o.z = fmaf(wt, vv.z, o.z);
                o.w = fmaf(wt, vv.w, o.w);
            }
        }
    }

    // B2 stored once (hi); GEMM2's A (wo) carries the lo split.
    __half2 p0 = __floats2half2_rn(o.x, o.y);
    __half2 p1 = __floats2half2_rn(o.z, o.w);
    __half2* dst = (__half2*)(aoT + (size_t)(b * HW + y * IMG_W + x) * INNER + chb);
    dst[0] = p0;
    dst[1] = p1;
}

// ---------------- launch ----------------
extern "C" void kernel_launch(void* const* d_in, const int* in_sizes, int n_in,
                              void* d_out, int out_size)
{
    const float* x   = (const float*)d_in[0];
    const float* Wq  = (const float*)d_in[1];
    const float* Wkv = (const float*)d_in[2];
    const float* Wo  = (const float*)d_in[3];
    const float* bo  = (const float*)d_in[4];
    float* out = (float*)d_out;

    __half *xT, *wqkv, *wo, *aoT;
    float* qkvT;
    cudaGetSymbolAddress((void**)&xT,   g_xT);
    cudaGetSymbolAddress((void**)&wqkv, g_wqkv);
    cudaGetSymbolAddress((void**)&wo,   g_wo);
    cudaGetSymbolAddress((void**)&qkvT, g_qkvT);
    cudaGetSymbolAddress((void**)&aoT,  g_aoT);

    const int gemm_smem = 3 * STG;   // 144 KB
    cudaFuncSetAttribute((const void*)hmma_gemm<K1P / 64, DIMC, 0>,
                         cudaFuncAttributeMaxDynamicSharedMemorySize, gemm_smem);
    cudaFuncSetAttribute((const void*)hmma_gemm<K2P / 64, INNER, 1>,
                         cudaFuncAttributeMaxDynamicSharedMemorySize, gemm_smem);

    // 0) converts
    weights_convert<<<QKV_CH + DIMC, 512>>>(Wq, Wkv, Wo, wqkv, wo);
    transpose_convert<<<dim3(HW / 32, DIMC / 32, BATCH), dim3(32, 8)>>>(x, xT);

    // 1) qkv projection: D[p][ch], M=12544, N=1536, K'=768 (B dedup 384)
    hmma_gemm<K1P / 64, DIMC, 0><<<dim3(QKV_CH / 256, NPIX / 128), 256, gemm_smem>>>(
        xT, K1P, wqkv, DIMC, nullptr, qkvT, QKV_CH);

    // 2) neighborhood attention (warp per pixel-head-pair)
    attn_kernel<<<dim3(IMG_W / 2, IMG_H, BATCH), 256>>>(qkvT, aoT);

    // 3) out projection: D[ch][p] -> out (channel-major) + bias, K'=1024 (B dedup 512)
    hmma_gemm<K2P / 64, INNER, 1><<<dim3(NPIX / 256, DIMC / 128), 256, gemm_smem>>>(
        wo, K2P, aoT, INNER, bo, out, 0);
}

// round 10
// speedup vs baseline: 3.7116x; 1.0501x over previous
#include <cuda_runtime.h>
#include <cuda_fp16.h>
#include <cstdint>
#include <cstddef>

#define BATCH   4
#define DIMC    384
#define HEADS   8
#define DHEAD   64
#define INNER   512
#define QKV_CH  1536
#define IMG_H   56
#define IMG_W   56
#define HW      3136
#define NPIX    (BATCH * HW)      // 12544
#define SCALE   0.125f

#define K1P     768               // A-side K' = 2*384 ([hi|lo]); B stored once (384)
#define K2P     1024              // A-side K' = 2*512 ([hi|lo]); B stored once (512)

// Scratch (device globals; allocation forbidden)
__device__ __half g_xT  [(size_t)NPIX * K1P];     // A1: [hi|lo] of x, pixel-major
__device__ __half g_wqkv[(size_t)QKV_CH * DIMC];  // B1: hi only (k-dedup)
__device__ __half g_wo  [(size_t)DIMC * K2P];     // A2: [hi|lo] of Wo
__device__ __half g_qkvT[(size_t)NPIX * QKV_CH];  // pixel-major q|k|v (fp16)
__device__ __half g_aoT [(size_t)NPIX * INNER];   // B2: hi only (k-dedup)

// ---------------- PTX helpers (baseline sm_80+ features only) ----------------
__device__ __forceinline__ uint32_t smem_u32(const void* p) {
    uint32_t a;
    asm("{ .reg .u64 t; cvta.to.shared.u64 t, %1; cvt.u32.u64 %0, t; }" : "=r"(a) : "l"(p));
    return a;
}
__device__ __forceinline__ void cp_async16(uint32_t saddr, const void* gptr) {
    asm volatile("cp.async.cg.shared.global [%0], [%1], 16;\n" :: "r"(saddr), "l"(gptr));
}
__device__ __forceinline__ void cp_commit() {
    asm volatile("cp.async.commit_group;\n" ::: "memory");
}
template <int N> __device__ __forceinline__ void cp_wait() {
    asm volatile("cp.async.wait_group %0;\n" :: "n"(N) : "memory");
}
__device__ __forceinline__ void ldsm_x4(uint32_t addr, uint32_t& r0, uint32_t& r1,
                                        uint32_t& r2, uint32_t& r3) {
    asm volatile("ldmatrix.sync.aligned.m8n8.x4.shared.b16 {%0,%1,%2,%3}, [%4];"
                 : "=r"(r0), "=r"(r1), "=r"(r2), "=r"(r3) : "r"(addr));
}
__device__ __forceinline__ void mma16816(float* d, const uint32_t* a, const uint32_t* b) {
    asm volatile("mma.sync.aligned.m16n8k16.row.col.f32.f16.f16.f32 "
        "{%0,%1,%2,%3}, {%4,%5,%6,%7}, {%8,%9}, {%0,%1,%2,%3};"
        : "+f"(d[0]), "+f"(d[1]), "+f"(d[2]), "+f"(d[3])
        : "r"(a[0]), "r"(a[1]), "r"(a[2]), "r"(a[3]), "r"(b[0]), "r"(b[1]));
}

// ---------------- input converts ----------------
__device__ __forceinline__ void split_f16(float v, __half& hi, __half& lo) {
    hi = __float2half(v);
    lo = __float2half(v - __half2float(hi));
}

__global__ __launch_bounds__(256) void transpose_convert(
    const float* __restrict__ x, __half* __restrict__ xT)
{
    __shared__ float t[32][33];
    const int p0 = blockIdx.x * 32, c0 = blockIdx.y * 32, b = blockIdx.z;
    const int tx = threadIdx.x, ty = threadIdx.y;
    const float* src = x + (size_t)b * DIMC * HW;
    #pragma unroll
    for (int i = 0; i < 32; i += 8)
        t[ty + i][tx] = src[(size_t)(c0 + ty + i) * HW + p0 + tx];
    __syncthreads();
    __half* dst = xT + (size_t)b * HW * K1P;
    #pragma unroll
    for (int i = 0; i < 32; i += 8) {
        const float v = t[tx][ty + i];
        __half hi, lo; split_f16(v, hi, lo);
        const size_t row = (size_t)(p0 + ty + i) * K1P;
        dst[row + c0 + tx]       = hi;   // A-side: [hi | lo]
        dst[row + 384 + c0 + tx] = lo;
    }
}

// Merged weight converts: blocks [0,1536) -> wqkv hi; [1536,1920) -> wo [hi|lo]
__global__ __launch_bounds__(512) void weights_convert(
    const float* __restrict__ Wq, const float* __restrict__ Wkv,
    const float* __restrict__ Wo,
    __half* __restrict__ wqkv, __half* __restrict__ wo)
{
    const int blk = blockIdx.x;
    const int k = threadIdx.x;
    if (blk < QKV_CH) {
        if (k < DIMC) {
            const float w = (blk < INNER) ? Wq[(size_t)blk * DIMC + k]
                                          : Wkv[(size_t)(blk - INNER) * DIMC + k];
            wqkv[(size_t)blk * DIMC + k] = __float2half(w);   // B1: hi only
        }
    } else {
        const int row = blk - QKV_CH;
        const float w = Wo[(size_t)row * INNER + k];
        __half hi, lo; split_f16(w, hi, lo);
        const size_t base = (size_t)row * K2P;
        wo[base + k]       = hi;                               // A2: [hi | lo]
        wo[base + 512 + k] = lo;
    }
}

// ---------------- mma.sync fp16 GEMM ----------------
// D[m][n] = sum_{k'} A[m][k'] * B[n][k' % KB]   (A K'=2*KB [hi|lo], B stored once)
// CTA tile 128x256, K-chunk 64, 3-stage cp.async. 8 warps 2(M)x4(N), warp 64x64.
// EPI 0: C is __half*, row-major ldc.  EPI 1: C is float*, channel-major + bias.
#define STG 49152   // per stage: A 128*128B (16KB) + B 256*128B (32KB)

__device__ __forceinline__ void stage_ld(uint32_t sA, uint32_t sB,
    const __half* __restrict__ Ag, int lda, int kta,
    const __half* __restrict__ Bg, int ldb, int ktb, int tid)
{
    #pragma unroll
    for (int i = 0; i < 4; i++) {
        const int idx = tid + i * 256;
        const int row = idx >> 3, j = idx & 7;
        const uint32_t off = (uint32_t)(row * 128 + ((j ^ (row & 7)) * 16));
        cp_async16(sA + off, Ag + (size_t)row * lda + kta + j * 8);
    }
    #pragma unroll
    for (int i = 0; i < 8; i++) {
        const int idx = tid + i * 256;
        const int row = idx >> 3, j = idx & 7;
        const uint32_t off = (uint32_t)(row * 128 + ((j ^ (row & 7)) * 16));
        cp_async16(sB + off, Bg + (size_t)row * ldb + ktb + j * 8);
    }
}

template <int T, int KB, int EPI>
__global__ __launch_bounds__(256) void hmma_gemm(
    const __half* __restrict__ A, int lda,
    const __half* __restrict__ B, int ldb,
    const float* __restrict__ bias, void* __restrict__ C, int ldc)
{
    extern __shared__ char dynraw[];
    const uint32_t smem = smem_u32(dynraw);
    const int tid = threadIdx.x;
    const int w = tid >> 5, l = tid & 31;
    const int wm = w >> 2, wn = w & 3;
    const int n0 = blockIdx.x * 256, m0 = blockIdx.y * 128;

    const __half* Ag = A + (size_t)m0 * lda;
    const __half* Bg = B + (size_t)n0 * ldb;

    float acc[4][8][4];
    #pragma unroll
    for (int i = 0; i < 4; i++)
        #pragma unroll
        for (int j = 0; j < 8; j++)
            #pragma unroll
            for (int c = 0; c < 4; c++) acc[i][j][c] = 0.f;

    // ldmatrix lane constants (all non-trans; K-major operands)
    const int arow_l = (l & 7) + ((l >> 3) & 1) * 8;   // A: row-in-16
    const int acol_l = (l >> 4) & 1;                   // A: k-half chunk
    const int brow_l = (l & 7) + ((l >> 4) & 1) * 8;   // B: n-row-in-16
    const int bcol_l = (l >> 3) & 1;                   // B: k-half chunk

    int abase[4], asw[4];
    #pragma unroll
    for (int i = 0; i < 4; i++) {
        const int mrow = wm * 64 + i * 16 + arow_l;
        abase[i] = mrow * 128;
        asw[i]   = mrow & 7;
    }
    int bbase[4], bsw[4];
    #pragma unroll
    for (int jj = 0; jj < 4; jj++) {
        const int nrow = wn * 64 + jj * 16 + brow_l;
        bbase[jj] = nrow * 128;
        bsw[jj]   = nrow & 7;
    }

    // ks-stagger: warps sharing an SMSP (w and w+4) start at different ks
    const int ks0 = ((w >> 2) & 1) << 1;

    // Prologue: stages 0, 1 (kt=0,64 both < KB)
    stage_ld(smem,       smem + 16384,       Ag, lda, 0,  Bg, ldb, 0,  tid); cp_commit();
    stage_ld(smem + STG, smem + STG + 16384, Ag, lda, 64, Bg, ldb, 64, tid); cp_commit();

    #pragma unroll 1
    for (int t = 0; t < T; t++) {
        cp_wait<1>();
        __syncthreads();
        if (t + 2 < T) {
            const int s2 = (t + 2) % 3;
            const int kt2 = (t + 2) * 64;
            const int ktb2 = (kt2 >= KB) ? kt2 - KB : kt2;
            stage_ld(smem + s2 * STG, smem + s2 * STG + 16384,
                     Ag, lda, kt2, Bg, ldb, ktb2, tid);
        }
        cp_commit();

        const uint32_t sA = smem + (t % 3) * STG;
        const uint32_t sB = sA + 16384;
        #pragma unroll
        for (int kss = 0; kss < 4; kss++) {
            const int ks = (kss + ks0) & 3;
            uint32_t af[4][4];
            #pragma unroll
            for (int i = 0; i < 4; i++)
                ldsm_x4(sA + abase[i] + (((ks * 2 + acol_l) ^ asw[i]) * 16),
                        af[i][0], af[i][1], af[i][2], af[i][3]);
            uint32_t bf[8][2];
            #pragma unroll
            for (int jj = 0; jj < 4; jj++)
                ldsm_x4(sB + bbase[jj] + (((ks * 2 + bcol_l) ^ bsw[jj]) * 16),
                        bf[jj * 2][0], bf[jj * 2][1], bf[jj * 2 + 1][0], bf[jj * 2 + 1][1]);
            #pragma unroll
            for (int i = 0; i < 4; i++)
                #pragma unroll
                for (int j = 0; j < 8; j++)
                    mma16816(acc[i][j], af[i], bf[j]);
        }
    }

    // Epilogue: lane l holds rows (l>>2) and (l>>2)+8, cols 2*(l&3)
    const int r4 = l >> 2;
    const int c2 = (l & 3) * 2;
    #pragma unroll
    for (int i = 0; i < 4; i++) {
        const int row_a = m0 + wm * 64 + i * 16 + r4;
        #pragma unroll
        for (int h = 0; h < 2; h++) {
            const int row = row_a + h * 8;
            #pragma unroll
            for (int j = 0; j < 8; j++) {
                const int col = n0 + wn * 64 + j * 8 + c2;
                if (EPI == 0) {
                    const __half2 hv = __floats2half2_rn(acc[i][j][h * 2],
                                                         acc[i][j][h * 2 + 1]);
                    *(__half2*)((__half*)C + (size_t)row * ldc + col) = hv;
                } else {
                    const float bv = bias[row];
                    const int bb = col / HW;
                    const int hw = col - bb * HW;
                    float2 v = make_float2(acc[i][j][h * 2] + bv,
                                           acc[i][j][h * 2 + 1] + bv);
                    *(float2*)((float*)C + ((size_t)bb * DIMC + row) * HW + hw) = v;
                }
            }
        }
    }
}

// ---------------- attention: warp per (pixel, head-pair), fp16 qkv ----------------
// Lane owns 4 consecutive d of ONE head: lanes 0-15 -> head 2*hp, 16-31 -> 2*hp+1.
__device__ __forceinline__ float4 ld_h4(const __half* p) {
    const uint2 raw = *(const uint2*)p;
    const float2 a = __half22float2(*(const __half2*)&raw.x);
    const float2 b = __half22float2(*(const __half2*)&raw.y);
    return make_float4(a.x, a.y, b.x, b.y);
}

__global__ __launch_bounds__(256) void attn_kernel(
    const __half* __restrict__ qkvT, __half* __restrict__ aoT)
{
    const int w  = threadIdx.x >> 5;
    const int l  = threadIdx.x & 31;
    const int x  = blockIdx.x * 2 + (w >> 2);
    const int y  = blockIdx.y;
    const int b  = blockIdx.z;
    const int hp = w & 3;                  // head pair 0..3
    const int chb = hp * 128 + l * 4;      // offset within 512-channel block

    const __half* base = qkvT + (size_t)(b * HW + y * IMG_W + x) * QKV_CH;
    const float4 q = ld_h4(base + chb);

    const bool interior = (x >= 1) && (x <= IMG_W - 2) && (y >= 1) && (y <= IMG_H - 2);

    float dots[9];
    if (interior) {
        #pragma unroll
        for (int r = 0; r < 3; r++) {
            const __half* krow = base + ((r - 1) * IMG_W - 1) * QKV_CH + INNER + chb;
            #pragma unroll
            for (int c = 0; c < 3; c++) {
                const float4 kk = ld_h4(krow + c * QKV_CH);
                dots[r * 3 + c] = fmaf(q.x, kk.x,
                                  fmaf(q.y, kk.y,
                                  fmaf(q.z, kk.z, q.w * kk.w)));
            }
        }
    } else {
        #pragma unroll
        for (int t = 0; t < 9; t++) {
            const int yy = y + t / 3 - 1;
            const int xx = x + t % 3 - 1;
            float d = 0.f;
            if (yy >= 0 && yy < IMG_H && xx >= 0 && xx < IMG_W) {
                const float4 kk = ld_h4(
                    qkvT + (size_t)(b * HW + yy * IMG_W + xx) * QKV_CH + INNER + chb);
                d = fmaf(q.x, kk.x, fmaf(q.y, kk.y, fmaf(q.z, kk.z, q.w * kk.w)));
            }
            dots[t] = d;
        }
    }

    // 4-stage butterfly within each 16-lane (one-head) group
    #pragma unroll
    for (int off = 8; off; off >>= 1)
        #pragma unroll
        for (int t = 0; t < 9; t++)
            dots[t] += __shfl_xor_sync(0xFFFFFFFFu, dots[t], off);

    float m = -1e30f;
    #pragma unroll
    for (int t = 0; t < 9; t++) { dots[t] *= SCALE; m = fmaxf(m, dots[t]); }
    float wgt[9], s = 0.f;
    #pragma unroll
    for (int t = 0; t < 9; t++) { wgt[t] = __expf(dots[t] - m); s += wgt[t]; }
    const float inv = 1.f / s;
    #pragma unroll
    for (int t = 0; t < 9; t++) wgt[t] *= inv;

    float4 o = make_float4(0.f, 0.f, 0.f, 0.f);
    if (interior) {
        #pragma unroll
        for (int r = 0; r < 3; r++) {
            const __half* vrow = base + ((r - 1) * IMG_W - 1) * QKV_CH + 2 * INNER + chb;
            #pragma unroll
            for (int c = 0; c < 3; c++) {
                const float4 vv = ld_h4(vrow + c * QKV_CH);
                const float wt = wgt[r * 3 + c];
                o.x = fmaf(wt, vv.x, o.x);
                o.y = fmaf(wt, vv.y, o.y);
                o.z = fmaf(wt, vv.z, o.z);
                o.w = fmaf(wt, vv.w, o.w);
            }
        }
    } else {
        #pragma unroll
        for (int t = 0; t < 9; t++) {
            const int yy = y + t / 3 - 1;
            const int xx = x + t % 3 - 1;
            if (yy >= 0 && yy < IMG_H && xx >= 0 && xx < IMG_W) {
                const float4 vv = ld_h4(
                    qkvT + (size_t)(b * HW + yy * IMG_W + xx) * QKV_CH + 2 * INNER + chb);
                const float wt = wgt[t];
                o.x = fmaf(wt, vv.x, o.x);
                o.y = fmaf(wt, vv.y, o.y);
                o.z = fmaf(wt, vv.z, o.z);
                o.w = fmaf(wt, vv.w, o.w);
            }
        }
    }

    // B2 stored once (hi); GEMM2's A (wo) carries the lo split.
    __half2 p0 = __floats2half2_rn(o.x, o.y);
    __half2 p1 = __floats2half2_rn(o.z, o.w);
    __half2* dst = (__half2*)(aoT + (size_t)(b * HW + y * IMG_W + x) * INNER + chb);
    dst[0] = p0;
    dst[1] = p1;
}

// ---------------- launch ----------------
extern "C" void kernel_launch(void* const* d_in, const int* in_sizes, int n_in,
                              void* d_out, int out_size)
{
    const float* x   = (const float*)d_in[0];
    const float* Wq  = (const float*)d_in[1];
    const float* Wkv = (const float*)d_in[2];
    const float* Wo  = (const float*)d_in[3];
    const float* bo  = (const float*)d_in[4];
    float* out = (float*)d_out;

    __half *xT, *wqkv, *wo, *qkvT, *aoT;
    cudaGetSymbolAddress((void**)&xT,   g_xT);
    cudaGetSymbolAddress((void**)&wqkv, g_wqkv);
    cudaGetSymbolAddress((void**)&wo,   g_wo);
    cudaGetSymbolAddress((void**)&qkvT, g_qkvT);
    cudaGetSymbolAddress((void**)&aoT,  g_aoT);

    const int gemm_smem = 3 * STG;   // 144 KB
    cudaFuncSetAttribute((const void*)hmma_gemm<K1P / 64, DIMC, 0>,
                         cudaFuncAttributeMaxDynamicSharedMemorySize, gemm_smem);
    cudaFuncSetAttribute((const void*)hmma_gemm<K2P / 64, INNER, 1>,
                         cudaFuncAttributeMaxDynamicSharedMemorySize, gemm_smem);

    // 0) converts
    weights_convert<<<QKV_CH + DIMC, 512>>>(Wq, Wkv, Wo, wqkv, wo);
    transpose_convert<<<dim3(HW / 32, DIMC / 32, BATCH), dim3(32, 8)>>>(x, xT);

    // 1) qkv projection: D[p][ch] fp16, M=12544, N=1536, K'=768 (B dedup 384)
    hmma_gemm<K1P / 64, DIMC, 0><<<dim3(QKV_CH / 256, NPIX / 128), 256, gemm_smem>>>(
        xT, K1P, wqkv, DIMC, nullptr, qkvT, QKV_CH);

    // 2) neighborhood attention (warp per pixel-head-pair, fp16 qkv)
    attn_kernel<<<dim3(IMG_W / 2, IMG_H, BATCH), 256>>>(qkvT, aoT);

    // 3) out projection: D[ch][p] -> out (channel-major) + bias, K'=1024 (B dedup 512)
    hmma_gemm<K2P / 64, INNER, 1><<<dim3(NPIX / 256, DIMC / 128), 256, gemm_smem>>>(
        wo, K2P, aoT, INNER, bo, out, 0);
}

// round 11
// speedup vs baseline: 4.8220x; 1.2992x over previous
#include <cuda_runtime.h>
#include <cuda_fp16.h>
#include <cstdint>
#include <cstddef>

#define BATCH   4
#define DIMC    384
#define HEADS   8
#define DHEAD   64
#define INNER   512
#define QKV_CH  1536
#define IMG_H   56
#define IMG_W   56
#define HW      3136
#define NPIX    (BATCH * HW)      // 12544
#define SCALE   0.125f

#define K1P     384               // GEMM1: plain fp16 (hi only) — output is fp16 anyway
#define K2P     1024              // GEMM2: A-side K' = 2*512 ([hi|lo]); B stored once (512)

// Scratch (device globals; allocation forbidden)
__device__ __half g_xT  [(size_t)NPIX * K1P];     // A1: hi of x, pixel-major
__device__ __half g_wqkv[(size_t)QKV_CH * DIMC];  // B1: hi
__device__ __half g_wo  [(size_t)DIMC * K2P];     // A2: [hi|lo] of Wo
__device__ __half g_qkvT[(size_t)NPIX * QKV_CH];  // pixel-major q|k|v (fp16)
__device__ __half g_aoT [(size_t)NPIX * INNER];   // B2: hi only (k-dedup)

// ---------------- PTX helpers (baseline sm_80+ features only) ----------------
__device__ __forceinline__ uint32_t smem_u32(const void* p) {
    uint32_t a;
    asm("{ .reg .u64 t; cvta.to.shared.u64 t, %1; cvt.u32.u64 %0, t; }" : "=r"(a) : "l"(p));
    return a;
}
__device__ __forceinline__ void cp_async16(uint32_t saddr, const void* gptr) {
    asm volatile("cp.async.cg.shared.global [%0], [%1], 16;\n" :: "r"(saddr), "l"(gptr));
}
__device__ __forceinline__ void cp_commit() {
    asm volatile("cp.async.commit_group;\n" ::: "memory");
}
template <int N> __device__ __forceinline__ void cp_wait() {
    asm volatile("cp.async.wait_group %0;\n" :: "n"(N) : "memory");
}
__device__ __forceinline__ void ldsm_x4(uint32_t addr, uint32_t& r0, uint32_t& r1,
                                        uint32_t& r2, uint32_t& r3) {
    asm volatile("ldmatrix.sync.aligned.m8n8.x4.shared.b16 {%0,%1,%2,%3}, [%4];"
                 : "=r"(r0), "=r"(r1), "=r"(r2), "=r"(r3) : "r"(addr));
}
__device__ __forceinline__ void mma16816(float* d, const uint32_t* a, const uint32_t* b) {
    asm volatile("mma.sync.aligned.m16n8k16.row.col.f32.f16.f16.f32 "
        "{%0,%1,%2,%3}, {%4,%5,%6,%7}, {%8,%9}, {%0,%1,%2,%3};"
        : "+f"(d[0]), "+f"(d[1]), "+f"(d[2]), "+f"(d[3])
        : "r"(a[0]), "r"(a[1]), "r"(a[2]), "r"(a[3]), "r"(b[0]), "r"(b[1]));
}

// ---------------- input converts ----------------
__device__ __forceinline__ void split_f16(float v, __half& hi, __half& lo) {
    hi = __float2half(v);
    lo = __float2half(v - __half2float(hi));
}

__global__ __launch_bounds__(256) void transpose_convert(
    const float* __restrict__ x, __half* __restrict__ xT)
{
    __shared__ float t[32][33];
    const int p0 = blockIdx.x * 32, c0 = blockIdx.y * 32, b = blockIdx.z;
    const int tx = threadIdx.x, ty = threadIdx.y;
    const float* src = x + (size_t)b * DIMC * HW;
    #pragma unroll
    for (int i = 0; i < 32; i += 8)
        t[ty + i][tx] = src[(size_t)(c0 + ty + i) * HW + p0 + tx];
    __syncthreads();
    __half* dst = xT + (size_t)b * HW * K1P;
    #pragma unroll
    for (int i = 0; i < 32; i += 8) {
        const size_t row = (size_t)(p0 + ty + i) * K1P;
        dst[row + c0 + tx] = __float2half(t[tx][ty + i]);   // hi only
    }
}

// Merged weight converts: blocks [0,1536) -> wqkv hi; [1536,1920) -> wo [hi|lo]
__global__ __launch_bounds__(512) void weights_convert(
    const float* __restrict__ Wq, const float* __restrict__ Wkv,
    const float* __restrict__ Wo,
    __half* __restrict__ wqkv, __half* __restrict__ wo)
{
    const int blk = blockIdx.x;
    const int k = threadIdx.x;
    if (blk < QKV_CH) {
        if (k < DIMC) {
            const float w = (blk < INNER) ? Wq[(size_t)blk * DIMC + k]
                                          : Wkv[(size_t)(blk - INNER) * DIMC + k];
            wqkv[(size_t)blk * DIMC + k] = __float2half(w);   // B1: hi
        }
    } else {
        const int row = blk - QKV_CH;
        const float w = Wo[(size_t)row * INNER + k];
        __half hi, lo; split_f16(w, hi, lo);
        const size_t base = (size_t)row * K2P;
        wo[base + k]       = hi;                               // A2: [hi | lo]
        wo[base + 512 + k] = lo;
    }
}

// ---------------- mma.sync fp16 GEMM ----------------
// D[m][n] = sum_{k'} A[m][k'] * B[n][k' % KB]   (B wraps when K' > KB)
// CTA tile 128x256, K-chunk 64, 3-stage cp.async. 8 warps 2(M)x4(N), warp 64x64.
// EPI 0: C is __half*, row-major ldc.  EPI 1: C is float*, channel-major + bias.
#define STG 49152   // per stage: A 128*128B (16KB) + B 256*128B (32KB)

__device__ __forceinline__ void stage_ld(uint32_t sA, uint32_t sB,
    const __half* __restrict__ Ag, int lda, int kta,
    const __half* __restrict__ Bg, int ldb, int ktb, int tid)
{
    #pragma unroll
    for (int i = 0; i < 4; i++) {
        const int idx = tid + i * 256;
        const int row = idx >> 3, j = idx & 7;
        const uint32_t off = (uint32_t)(row * 128 + ((j ^ (row & 7)) * 16));
        cp_async16(sA + off, Ag + (size_t)row * lda + kta + j * 8);
    }
    #pragma unroll
    for (int i = 0; i < 8; i++) {
        const int idx = tid + i * 256;
        const int row = idx >> 3, j = idx & 7;
        const uint32_t off = (uint32_t)(row * 128 + ((j ^ (row & 7)) * 16));
        cp_async16(sB + off, Bg + (size_t)row * ldb + ktb + j * 8);
    }
}

template <int T, int KB, int EPI>
__global__ __launch_bounds__(256) void hmma_gemm(
    const __half* __restrict__ A, int lda,
    const __half* __restrict__ B, int ldb,
    const float* __restrict__ bias, void* __restrict__ C, int ldc)
{
    extern __shared__ char dynraw[];
    const uint32_t smem = smem_u32(dynraw);
    const int tid = threadIdx.x;
    const int w = tid >> 5, l = tid & 31;
    const int wm = w >> 2, wn = w & 3;
    const int n0 = blockIdx.x * 256, m0 = blockIdx.y * 128;

    const __half* Ag = A + (size_t)m0 * lda;
    const __half* Bg = B + (size_t)n0 * ldb;

    float acc[4][8][4];
    #pragma unroll
    for (int i = 0; i < 4; i++)
        #pragma unroll
        for (int j = 0; j < 8; j++)
            #pragma unroll
            for (int c = 0; c < 4; c++) acc[i][j][c] = 0.f;

    // ldmatrix lane constants (all non-trans; K-major operands)
    const int arow_l = (l & 7) + ((l >> 3) & 1) * 8;   // A: row-in-16
    const int acol_l = (l >> 4) & 1;                   // A: k-half chunk
    const int brow_l = (l & 7) + ((l >> 4) & 1) * 8;   // B: n-row-in-16
    const int bcol_l = (l >> 3) & 1;                   // B: k-half chunk

    int abase[4], asw[4];
    #pragma unroll
    for (int i = 0; i < 4; i++) {
        const int mrow = wm * 64 + i * 16 + arow_l;
        abase[i] = mrow * 128;
        asw[i]   = mrow & 7;
    }
    int bbase[4], bsw[4];
    #pragma unroll
    for (int jj = 0; jj < 4; jj++) {
        const int nrow = wn * 64 + jj * 16 + brow_l;
        bbase[jj] = nrow * 128;
        bsw[jj]   = nrow & 7;
    }

    // ks-stagger: warps sharing an SMSP (w and w+4) start at different ks
    const int ks0 = ((w >> 2) & 1) << 1;

    // Prologue: stages 0, 1 (kt=0,64 both < KB)
    stage_ld(smem,       smem + 16384,       Ag, lda, 0,  Bg, ldb, 0,  tid); cp_commit();
    stage_ld(smem + STG, smem + STG + 16384, Ag, lda, 64, Bg, ldb, 64, tid); cp_commit();

    #pragma unroll 1
    for (int t = 0; t < T; t++) {
        cp_wait<1>();
        __syncthreads();
        if (t + 2 < T) {
            const int s2 = (t + 2) % 3;
            const int kt2 = (t + 2) * 64;
            const int ktb2 = (kt2 >= KB) ? kt2 - KB : kt2;
            stage_ld(smem + s2 * STG, smem + s2 * STG + 16384,
                     Ag, lda, kt2, Bg, ldb, ktb2, tid);
        }
        cp_commit();

        const uint32_t sA = smem + (t % 3) * STG;
        const uint32_t sB = sA + 16384;
        #pragma unroll
        for (int kss = 0; kss < 4; kss++) {
            const int ks = (kss + ks0) & 3;
            uint32_t af[4][4];
            #pragma unroll
            for (int i = 0; i < 4; i++)
                ldsm_x4(sA + abase[i] + (((ks * 2 + acol_l) ^ asw[i]) * 16),
                        af[i][0], af[i][1], af[i][2], af[i][3]);
            uint32_t bf[8][2];
            #pragma unroll
            for (int jj = 0; jj < 4; jj++)
                ldsm_x4(sB + bbase[jj] + (((ks * 2 + bcol_l) ^ bsw[jj]) * 16),
                        bf[jj * 2][0], bf[jj * 2][1], bf[jj * 2 + 1][0], bf[jj * 2 + 1][1]);
            #pragma unroll
            for (int i = 0; i < 4; i++)
                #pragma unroll
                for (int j = 0; j < 8; j++)
                    mma16816(acc[i][j], af[i], bf[j]);
        }
    }

    // Epilogue: lane l holds rows (l>>2) and (l>>2)+8, cols 2*(l&3)
    const int r4 = l >> 2;
    const int c2 = (l & 3) * 2;
    #pragma unroll
    for (int i = 0; i < 4; i++) {
        const int row_a = m0 + wm * 64 + i * 16 + r4;
        #pragma unroll
        for (int h = 0; h < 2; h++) {
            const int row = row_a + h * 8;
            #pragma unroll
            for (int j = 0; j < 8; j++) {
                const int col = n0 + wn * 64 + j * 8 + c2;
                if (EPI == 0) {
                    const __half2 hv = __floats2half2_rn(acc[i][j][h * 2],
                                                         acc[i][j][h * 2 + 1]);
                    *(__half2*)((__half*)C + (size_t)row * ldc + col) = hv;
                } else {
                    const float bv = bias[row];
                    const int bb = col / HW;
                    const int hw = col - bb * HW;
                    float2 v = make_float2(acc[i][j][h * 2] + bv,
                                           acc[i][j][h * 2 + 1] + bv);
                    *(float2*)((float*)C + ((size_t)bb * DIMC + row) * HW + hw) = v;
                }
            }
        }
    }
}

// ---------------- attention: warp per (pixel, head-pair), fp16 qkv ----------------
// Lane owns 4 consecutive d of ONE head: lanes 0-15 -> head 2*hp, 16-31 -> 2*hp+1.
__device__ __forceinline__ float4 ld_h4(const __half* p) {
    const uint2 raw = *(const uint2*)p;
    const float2 a = __half22float2(*(const __half2*)&raw.x);
    const float2 b = __half22float2(*(const __half2*)&raw.y);
    return make_float4(a.x, a.y, b.x, b.y);
}

__global__ __launch_bounds__(256) void attn_kernel(
    const __half* __restrict__ qkvT, __half* __restrict__ aoT)
{
    const int w  = threadIdx.x >> 5;
    const int l  = threadIdx.x & 31;
    const int x  = blockIdx.x * 2 + (w >> 2);
    const int y  = blockIdx.y;
    const int b  = blockIdx.z;
    const int hp = w & 3;                  // head pair 0..3
    const int chb = hp * 128 + l * 4;      // offset within 512-channel block

    const __half* base = qkvT + (size_t)(b * HW + y * IMG_W + x) * QKV_CH;
    const float4 q = ld_h4(base + chb);

    const bool interior = (x >= 1) && (x <= IMG_W - 2) && (y >= 1) && (y <= IMG_H - 2);

    float dots[9];
    if (interior) {
        #pragma unroll
        for (int r = 0; r < 3; r++) {
            const __half* krow = base + ((r - 1) * IMG_W - 1) * QKV_CH + INNER + chb;
            #pragma unroll
            for (int c = 0; c < 3; c++) {
                const float4 kk = ld_h4(krow + c * QKV_CH);
                dots[r * 3 + c] = fmaf(q.x, kk.x,
                                  fmaf(q.y, kk.y,
                                  fmaf(q.z, kk.z, q.w * kk.w)));
            }
        }
    } else {
        #pragma unroll
        for (int t = 0; t < 9; t++) {
            const int yy = y + t / 3 - 1;
            const int xx = x + t % 3 - 1;
            float d = 0.f;
            if (yy >= 0 && yy < IMG_H && xx >= 0 && xx < IMG_W) {
                const float4 kk = ld_h4(
                    qkvT + (size_t)(b * HW + yy * IMG_W + xx) * QKV_CH + INNER + chb);
                d = fmaf(q.x, kk.x, fmaf(q.y, kk.y, fmaf(q.z, kk.z, q.w * kk.w)));
            }
            dots[t] = d;
        }
    }

    // 4-stage butterfly within each 16-lane (one-head) group
    #pragma unroll
    for (int off = 8; off; off >>= 1)
        #pragma unroll
        for (int t = 0; t < 9; t++)
            dots[t] += __shfl_xor_sync(0xFFFFFFFFu, dots[t], off);

    float m = -1e30f;
    #pragma unroll
    for (int t = 0; t < 9; t++) { dots[t] *= SCALE; m = fmaxf(m, dots[t]); }
    float wgt[9], s = 0.f;
    #pragma unroll
    for (int t = 0; t < 9; t++) { wgt[t] = __expf(dots[t] - m); s += wgt[t]; }
    const float inv = 1.f / s;
    #pragma unroll
    for (int t = 0; t < 9; t++) wgt[t] *= inv;

    float4 o = make_float4(0.f, 0.f, 0.f, 0.f);
    if (interior) {
        #pragma unroll
        for (int r = 0; r < 3; r++) {
            const __half* vrow = base + ((r - 1) * IMG_W - 1) * QKV_CH + 2 * INNER + chb;
            #pragma unroll
            for (int c = 0; c < 3; c++) {
                const float4 vv = ld_h4(vrow + c * QKV_CH);
                const float wt = wgt[r * 3 + c];
                o.x = fmaf(wt, vv.x, o.x);
                o.y = fmaf(wt, vv.y, o.y);
                o.z = fmaf(wt, vv.z, o.z);
                o.w = fmaf(wt, vv.w, o.w);
            }
        }
    } else {
        #pragma unroll
        for (int t = 0; t < 9; t++) {
            const int yy = y + t / 3 - 1;
            const int xx = x + t % 3 - 1;
            if (yy >= 0 && yy < IMG_H && xx >= 0 && xx < IMG_W) {
                const float4 vv = ld_h4(
                    qkvT + (size_t)(b * HW + yy * IMG_W + xx) * QKV_CH + 2 * INNER + chb);
                const float wt = wgt[t];
                o.x = fmaf(wt, vv.x, o.x);
                o.y = fmaf(wt, vv.y, o.y);
                o.z = fmaf(wt, vv.z, o.z);
                o.w = fmaf(wt, vv.w, o.w);
            }
        }
    }

    // B2 stored once (hi); GEMM2's A (wo) carries the lo split.
    __half2 p0 = __floats2half2_rn(o.x, o.y);
    __half2 p1 = __floats2half2_rn(o.z, o.w);
    __half2* dst = (__half2*)(aoT + (size_t)(b * HW + y * IMG_W + x) * INNER + chb);
    dst[0] = p0;
    dst[1] = p1;
}

// ---------------- launch ----------------
extern "C" void kernel_launch(void* const* d_in, const int* in_sizes, int n_in,
                              void* d_out, int out_size)
{
    const float* x   = (const float*)d_in[0];
    const float* Wq  = (const float*)d_in[1];
    const float* Wkv = (const float*)d_in[2];
    const float* Wo  = (const float*)d_in[3];
    const float* bo  = (const float*)d_in[4];
    float* out = (float*)d_out;

    __half *xT, *wqkv, *wo, *qkvT, *aoT;
    cudaGetSymbolAddress((void**)&xT,   g_xT);
    cudaGetSymbolAddress((void**)&wqkv, g_wqkv);
    cudaGetSymbolAddress((void**)&wo,   g_wo);
    cudaGetSymbolAddress((void**)&qkvT, g_qkvT);
    cudaGetSymbolAddress((void**)&aoT,  g_aoT);

    const int gemm_smem = 3 * STG;   // 144 KB
    cudaFuncSetAttribute((const void*)hmma_gemm<K1P / 64, K1P, 0>,
                         cudaFuncAttributeMaxDynamicSharedMemorySize, gemm_smem);
    cudaFuncSetAttribute((const void*)hmma_gemm<K2P / 64, INNER, 1>,
                         cudaFuncAttributeMaxDynamicSharedMemorySize, gemm_smem);

    // 0) converts
    weights_convert<<<QKV_CH + DIMC, 512>>>(Wq, Wkv, Wo, wqkv, wo);
    transpose_convert<<<dim3(HW / 32, DIMC / 32, BATCH), dim3(32, 8)>>>(x, xT);

    // 1) qkv projection: D[p][ch] fp16, M=12544, N=1536, K=384 (plain fp16)
    hmma_gemm<K1P / 64, K1P, 0><<<dim3(QKV_CH / 256, NPIX / 128), 256, gemm_smem>>>(
        xT, K1P, wqkv, DIMC, nullptr, qkvT, QKV_CH);

    // 2) neighborhood attention (warp per pixel-head-pair, fp16 qkv)
    attn_kernel<<<dim3(IMG_W / 2, IMG_H, BATCH), 256>>>(qkvT, aoT);

    // 3) out projection: D[ch][p] -> out (channel-major) + bias, K'=1024 (B dedup 512)
    hmma_gemm<K2P / 64, INNER, 1><<<dim3(NPIX / 256, DIMC / 128), 256, gemm_smem>>>(
        wo, K2P, aoT, INNER, bo, out, 0);
}